// round 1
// baseline (speedup 1.0000x reference)
#include <cuda_runtime.h>

#define BB 2
#define TT 2048
#define CC 1024
#define HH 16
#define DD 64
#define BHTD (BB*HH*TT*DD)   // 4,194,304

// Scratch (allocation-free rule: __device__ globals)
__device__ float g_qkv[3ll * BHTD];                 // [3,B,H,T,D]
__device__ float g_att[(long long)BB * TT * CC];    // [B,T,C]

// ---------------------------------------------------------------------------
// Tiled fp32 GEMM: C[M,N] = A[M,K] @ B[K,N] + bias[N]
// Block tile 128x128, K-tile 16, 256 threads, 8x8 per-thread microtile.
// QKV_EP=true: scatter into g_qkv [3,B,H,T,D].  QKV_EP=false: write Cout.
// All dims divisible by tiles (M=4096, N in {3072,1024}, K=1024): no guards.
// ---------------------------------------------------------------------------
template<int KDIM, bool QKV_EP>
__global__ void __launch_bounds__(256) sgemm_kernel(
    const float* __restrict__ A,
    const float* __restrict__ Bm,
    const float* __restrict__ bias,
    float* __restrict__ Cout,
    int N)
{
    __shared__ float As[16 * 128];   // transposed: As[k][m]
    __shared__ float Bs[16 * 128];   // Bs[k][n]

    const int tid = threadIdx.x;
    const int row = tid >> 4;        // 0..15
    const int col = tid & 15;        // 0..15
    const int m0 = blockIdx.y * 128;
    const int n0 = blockIdx.x * 128;

    float acc[8][8];
    #pragma unroll
    for (int i = 0; i < 8; i++)
        #pragma unroll
        for (int j = 0; j < 8; j++) acc[i][j] = 0.f;

    for (int k0 = 0; k0 < KDIM; k0 += 16) {
        // Load A tile (128 rows x 16 k) -> transposed into As
        #pragma unroll
        for (int i = 0; i < 2; i++) {
            int idx = tid + i * 256;            // 0..511
            int r  = idx >> 2;                  // 0..127
            int c4 = idx & 3;                   // 0..3
            float4 a = *(const float4*)(A + (size_t)(m0 + r) * KDIM + k0 + c4 * 4);
            As[(c4 * 4 + 0) * 128 + r] = a.x;
            As[(c4 * 4 + 1) * 128 + r] = a.y;
            As[(c4 * 4 + 2) * 128 + r] = a.z;
            As[(c4 * 4 + 3) * 128 + r] = a.w;
        }
        // Load B tile (16 k x 128 n)
        #pragma unroll
        for (int i = 0; i < 2; i++) {
            int idx = tid + i * 256;            // 0..511
            int r  = idx >> 5;                  // 0..15
            int c4 = idx & 31;                  // 0..31
            *(float4*)(Bs + r * 128 + c4 * 4) =
                *(const float4*)(Bm + (size_t)(k0 + r) * N + n0 + c4 * 4);
        }
        __syncthreads();

        #pragma unroll
        for (int kk = 0; kk < 16; kk++) {
            float4 a0 = *(const float4*)(As + kk * 128 + row * 8);
            float4 a1 = *(const float4*)(As + kk * 128 + row * 8 + 4);
            float4 b0 = *(const float4*)(Bs + kk * 128 + col * 8);
            float4 b1 = *(const float4*)(Bs + kk * 128 + col * 8 + 4);
            float av[8] = {a0.x, a0.y, a0.z, a0.w, a1.x, a1.y, a1.z, a1.w};
            float bv[8] = {b0.x, b0.y, b0.z, b0.w, b1.x, b1.y, b1.z, b1.w};
            #pragma unroll
            for (int i = 0; i < 8; i++)
                #pragma unroll
                for (int j = 0; j < 8; j++)
                    acc[i][j] += av[i] * bv[j];
        }
        __syncthreads();
    }

    // Epilogue
    #pragma unroll
    for (int i = 0; i < 8; i++) {
        int m = m0 + row * 8 + i;
        #pragma unroll
        for (int j = 0; j < 8; j++) {
            int n = n0 + col * 8 + j;
            float v = acc[i][j] + bias[n];
            if (QKV_EP) {
                int which = n >> 10;          // 0=q,1=k,2=v
                int hh = (n >> 6) & 15;
                int dd = n & 63;
                int bb = m >> 11;             // m / T
                int tt = m & 2047;            // m % T
                size_t dst = (((size_t)which * BB + bb) * HH + hh) * (size_t)(TT * DD)
                           + (size_t)tt * DD + dd;
                g_qkv[dst] = v;
            } else {
                Cout[(size_t)m * N + n] = v;
            }
        }
    }
}

// ---------------------------------------------------------------------------
// Flash attention fp32. One block = 64 queries of one (b,h). 64 threads,
// each thread owns one query row: q (64 regs) + acc (64 regs).
// K/V tiles (64x64) in smem, read via broadcast LDS.128.
// Score buffer XOR-swizzled for conflict-free per-thread rows.
// Total static smem = 3 * 16KB = 48KB exactly.
// ---------------------------------------------------------------------------
__global__ void __launch_bounds__(64) attn_kernel()
{
    __shared__ float ks[4096];
    __shared__ float vs[4096];
    __shared__ float ss[4096];

    const int tid  = threadIdx.x;
    const int lane = tid & 31;
    const int bh   = blockIdx.y;          // b*H + h
    const int q0   = blockIdx.x * 64;
    const int qi   = q0 + tid;

    const float NEG = -1e30f;

    // Load this thread's q row (scaled by 1/sqrt(D))
    const float* qp = g_qkv + ((size_t)bh * TT + qi) * DD;
    float qr[64];
    #pragma unroll
    for (int d4 = 0; d4 < 16; d4++) {
        float4 qv = *(const float4*)(qp + d4 * 4);
        qr[d4 * 4 + 0] = qv.x * 0.125f;
        qr[d4 * 4 + 1] = qv.y * 0.125f;
        qr[d4 * 4 + 2] = qv.z * 0.125f;
        qr[d4 * 4 + 3] = qv.w * 0.125f;
    }

    float acc[64];
    #pragma unroll
    for (int d = 0; d < 64; d++) acc[d] = 0.f;
    float m = NEG, l = 0.f;

    const float* kb = g_qkv + (size_t)BHTD       + (size_t)bh * TT * DD;
    const float* vb = g_qkv + (size_t)BHTD * 2   + (size_t)bh * TT * DD;

    float* my_ss = ss + tid * 64;

    for (int j0 = 0; j0 <= q0; j0 += 64) {
        // Cooperative contiguous tile loads (fully coalesced float4)
        const float4* k4 = (const float4*)(kb + (size_t)j0 * DD);
        const float4* v4 = (const float4*)(vb + (size_t)j0 * DD);
        #pragma unroll
        for (int i = 0; i < 16; i++) {
            ((float4*)ks)[tid + i * 64] = k4[tid + i * 64];
            ((float4*)vs)[tid + i * 64] = v4[tid + i * 64];
        }
        __syncthreads();

        // Scores for this thread's query vs 64 keys
        float tm = NEG;
        #pragma unroll 4
        for (int j = 0; j < 64; j++) {
            const float4* kr = (const float4*)(ks + j * 64);
            float s = 0.f;
            #pragma unroll
            for (int dd = 0; dd < 16; dd++) {
                float4 kv = kr[dd];
                s += qr[dd * 4 + 0] * kv.x;
                s += qr[dd * 4 + 1] * kv.y;
                s += qr[dd * 4 + 2] * kv.z;
                s += qr[dd * 4 + 3] * kv.w;
            }
            if (j0 + j > qi) s = NEG;       // causal mask
            my_ss[j ^ lane] = s;            // XOR swizzle: conflict-free
            tm = fmaxf(tm, s);
        }

        // Online softmax update
        float mn   = fmaxf(m, tm);
        float corr = __expf(m - mn);
        m = mn;
        float lsum = 0.f;
        #pragma unroll 8
        for (int j = 0; j < 64; j++) {
            float p = __expf(my_ss[j ^ lane] - mn);
            my_ss[j ^ lane] = p;
            lsum += p;
        }
        l = l * corr + lsum;
        #pragma unroll
        for (int d = 0; d < 64; d++) acc[d] *= corr;

        // acc += P @ V
        #pragma unroll 2
        for (int j = 0; j < 64; j++) {
            float p = my_ss[j ^ lane];
            const float4* vr = (const float4*)(vs + j * 64);
            #pragma unroll
            for (int dd = 0; dd < 16; dd++) {
                float4 vv = vr[dd];
                acc[dd * 4 + 0] += p * vv.x;
                acc[dd * 4 + 1] += p * vv.y;
                acc[dd * 4 + 2] += p * vv.z;
                acc[dd * 4 + 3] += p * vv.w;
            }
        }
        __syncthreads();
    }

    // Write out in [B,T,C] layout (ready for projection GEMM)
    float inv = 1.f / l;
    float* op = g_att + ((size_t)(bh >> 4) * TT + qi) * CC + (size_t)(bh & 15) * DD;
    #pragma unroll
    for (int d4 = 0; d4 < 16; d4++) {
        float4 o;
        o.x = acc[d4 * 4 + 0] * inv;
        o.y = acc[d4 * 4 + 1] * inv;
        o.z = acc[d4 * 4 + 2] * inv;
        o.w = acc[d4 * 4 + 3] * inv;
        *(float4*)(op + d4 * 4) = o;
    }
}

// ---------------------------------------------------------------------------
extern "C" void kernel_launch(void* const* d_in, const int* in_sizes, int n_in,
                              void* d_out, int out_size)
{
    const float* x      = (const float*)d_in[0];
    const float* w_attn = (const float*)d_in[1];
    const float* b_attn = (const float*)d_in[2];
    const float* w_proj = (const float*)d_in[3];
    const float* b_proj = (const float*)d_in[4];
    float* out = (float*)d_out;

    float* att_ptr = nullptr;
    cudaGetSymbolAddress((void**)&att_ptr, g_att);

    // 1) QKV GEMM + bias, scattered to [3,B,H,T,D]
    sgemm_kernel<1024, true><<<dim3(24, 32), 256>>>(x, w_attn, b_attn, nullptr, 3 * CC);

    // 2) Causal flash attention -> g_att [B,T,C]
    attn_kernel<<<dim3(TT / 64, BB * HH), 64>>>();

    // 3) Output projection + bias -> d_out
    sgemm_kernel<1024, false><<<dim3(8, 32), 256>>>(att_ptr, w_proj, b_proj, out, CC);
}

// round 3
// speedup vs baseline: 2.3932x; 2.3932x over previous
#include <cuda_runtime.h>
#include <cuda_bf16.h>
#include <cstdint>

#define BB 2
#define TT 2048
#define CC 1024
#define HH 16
#define DD 64
#define BHTD (BB*HH*TT*DD)   // 4,194,304

// ---------------------------------------------------------------------------
// Scratch (__device__ globals; allocation-free rule)
// ---------------------------------------------------------------------------
__device__ __align__(16) float g_qkv[3ll * BHTD];                    // [3,B,H,T,D] fp32
__device__ __align__(16) __nv_bfloat16 g_x_hi[4096ll * 1024];        // x split  [M,K]
__device__ __align__(16) __nv_bfloat16 g_x_lo[4096ll * 1024];
__device__ __align__(16) __nv_bfloat16 g_wq_hi[3072ll * 1024];       // w_attn^T [N,K]
__device__ __align__(16) __nv_bfloat16 g_wq_lo[3072ll * 1024];
__device__ __align__(16) __nv_bfloat16 g_wp_hi[1024ll * 1024];       // w_proj^T [N,K]
__device__ __align__(16) __nv_bfloat16 g_wp_lo[1024ll * 1024];
__device__ __align__(16) __nv_bfloat16 g_att_hi[4096ll * 1024];      // attn out split [M,K]
__device__ __align__(16) __nv_bfloat16 g_att_lo[4096ll * 1024];

// ---------------------------------------------------------------------------
// Helpers
// ---------------------------------------------------------------------------
__device__ __forceinline__ uint32_t smem_u32(const void* p) {
    uint32_t a;
    asm("{ .reg .u64 t; cvta.to.shared.u64 t, %1; cvt.u32.u64 %0, t; }" : "=r"(a) : "l"(p));
    return a;
}
__device__ __forceinline__ void cp_async16(uint32_t dst, const void* src) {
    asm volatile("cp.async.cg.shared.global [%0], [%1], 16;" :: "r"(dst), "l"(src));
}
#define CP_COMMIT() asm volatile("cp.async.commit_group;" ::: "memory")

__device__ __forceinline__ void ldsm4(uint32_t* r, uint32_t addr) {
    asm volatile("ldmatrix.sync.aligned.m8n8.x4.shared.b16 {%0,%1,%2,%3}, [%4];"
        : "=r"(r[0]), "=r"(r[1]), "=r"(r[2]), "=r"(r[3]) : "r"(addr));
}
__device__ __forceinline__ void mma16816(float* d, const uint32_t* a, const uint32_t* b) {
    asm volatile("mma.sync.aligned.m16n8k16.row.col.f32.bf16.bf16.f32 "
        "{%0,%1,%2,%3}, {%4,%5,%6,%7}, {%8,%9}, {%0,%1,%2,%3};"
        : "+f"(d[0]), "+f"(d[1]), "+f"(d[2]), "+f"(d[3])
        : "r"(a[0]), "r"(a[1]), "r"(a[2]), "r"(a[3]), "r"(b[0]), "r"(b[1]));
}

// ---------------------------------------------------------------------------
// Prepass: split fp32 -> (hi, lo) bf16
// ---------------------------------------------------------------------------
__global__ void split_kernel(const float* __restrict__ X,
                             __nv_bfloat16* __restrict__ hi,
                             __nv_bfloat16* __restrict__ lo)
{
    int i = blockIdx.x * blockDim.x + threadIdx.x;
    float4 v = ((const float4*)X)[i];
    __nv_bfloat16 h0 = __float2bfloat16_rn(v.x), h1 = __float2bfloat16_rn(v.y);
    __nv_bfloat16 h2 = __float2bfloat16_rn(v.z), h3 = __float2bfloat16_rn(v.w);
    __nv_bfloat16 l0 = __float2bfloat16_rn(v.x - __bfloat162float(h0));
    __nv_bfloat16 l1 = __float2bfloat16_rn(v.y - __bfloat162float(h1));
    __nv_bfloat16 l2 = __float2bfloat16_rn(v.z - __bfloat162float(h2));
    __nv_bfloat16 l3 = __float2bfloat16_rn(v.w - __bfloat162float(h3));
    *(__nv_bfloat162*)(hi + (size_t)i * 4)     = __halves2bfloat162(h0, h1);
    *(__nv_bfloat162*)(hi + (size_t)i * 4 + 2) = __halves2bfloat162(h2, h3);
    *(__nv_bfloat162*)(lo + (size_t)i * 4)     = __halves2bfloat162(l0, l1);
    *(__nv_bfloat162*)(lo + (size_t)i * 4 + 2) = __halves2bfloat162(l2, l3);
}

// Transpose + split: W [K,N] fp32 -> T_hi/T_lo [N,K] bf16
__global__ void tsplit_kernel(const float* __restrict__ W,
                              __nv_bfloat16* __restrict__ Thi,
                              __nv_bfloat16* __restrict__ Tlo,
                              int Ncols, int Krows)
{
    __shared__ float ts[32][33];
    int n0 = blockIdx.x * 32, k0 = blockIdx.y * 32;
    int tx = threadIdx.x, ty = threadIdx.y;
    ts[ty][tx] = W[(size_t)(k0 + ty) * Ncols + n0 + tx];
    __syncthreads();
    float v = ts[tx][ty];                       // = W[k0+tx][n0+ty]
    __nv_bfloat16 h = __float2bfloat16_rn(v);
    size_t o = (size_t)(n0 + ty) * Krows + k0 + tx;
    Thi[o] = h;
    Tlo[o] = __float2bfloat16_rn(v - __bfloat162float(h));
}

// ---------------------------------------------------------------------------
// bf16x3 GEMM via mma.sync: C[M,N] = A[M,1024] @ B^T (B stored [N,1024]) + bias
// Block tile 128x128, BK=32, 3-stage cp.async pipeline.
// 8 warps as 2(M) x 4(N); warp tile 64x32 = 4x4 m16n8 tiles.
// Smem rows padded to 80B -> ldmatrix conflict-free.
// QKV_EP: scatter into g_qkv [3,B,H,T,D]; else row-major store.
// ---------------------------------------------------------------------------
#define ROWB 80                    // padded row stride (bytes) for 32 bf16 = 64B
#define ARR  (128 * ROWB)          // 10240 bytes, one 128x32 bf16 tile
#define STAGE (4 * ARR)            // Ahi,Alo,Bhi,Blo
#define NSTG 3
#define GEMM_SMEM (NSTG * STAGE)   // 122880
#define NK 32                      // 1024 / 32

__device__ __forceinline__ void load_stage(
    int tid, int kt, uint32_t sbase,
    const __nv_bfloat16* Ahi, const __nv_bfloat16* Alo,
    const __nv_bfloat16* Bhi, const __nv_bfloat16* Blo,
    int m0, int n0)
{
    const uint32_t st = sbase + (uint32_t)((kt % NSTG) * STAGE);
    const int k0 = kt * 32;
    #pragma unroll
    for (int i = 0; i < 2; i++) {
        int chunk = tid + i * 256;                 // 0..511
        int r = chunk >> 2, c = chunk & 3;
        uint32_t d = (uint32_t)(r * ROWB + c * 16);
        size_t goA = (size_t)(m0 + r) * 1024 + k0 + c * 8;
        size_t goB = (size_t)(n0 + r) * 1024 + k0 + c * 8;
        cp_async16(st +           d, Ahi + goA);
        cp_async16(st + ARR     + d, Alo + goA);
        cp_async16(st + 2 * ARR + d, Bhi + goB);
        cp_async16(st + 3 * ARR + d, Blo + goB);
    }
    CP_COMMIT();
}

template<bool QKV_EP>
__global__ void __launch_bounds__(256) gemm_mma(
    const __nv_bfloat16* __restrict__ Ahi, const __nv_bfloat16* __restrict__ Alo,
    const __nv_bfloat16* __restrict__ Bhi, const __nv_bfloat16* __restrict__ Blo,
    const float* __restrict__ bias, float* __restrict__ Cout, int N)
{
    extern __shared__ __align__(128) char smem[];
    const uint32_t sb = smem_u32(smem);
    const int tid  = threadIdx.x;
    const int wid  = tid >> 5;
    const int lane = tid & 31;
    const int m0 = blockIdx.y * 128;
    const int n0 = blockIdx.x * 128;
    const int warpM = (wid >> 2) * 64;     // 0 or 64
    const int warpN = (wid & 3) * 32;      // 0,32,64,96

    float acc[4][4][4];
    #pragma unroll
    for (int i = 0; i < 4; i++)
        #pragma unroll
        for (int j = 0; j < 4; j++)
            #pragma unroll
            for (int e = 0; e < 4; e++) acc[i][j][e] = 0.f;

    // ldmatrix per-thread base offsets
    const uint32_t a_off = (uint32_t)((warpM + (lane & 15)) * ROWB + (lane >> 4) * 16);
    const int brow = (lane & 7) + ((lane >> 4) << 3);          // 0-7 / 8-15
    const uint32_t b_off = (uint32_t)((warpN + brow) * ROWB + ((lane >> 3) & 1) * 16);

    load_stage(tid, 0, sb, Ahi, Alo, Bhi, Blo, m0, n0);
    load_stage(tid, 1, sb, Ahi, Alo, Bhi, Blo, m0, n0);

    for (int kt = 0; kt < NK; kt++) {
        asm volatile("cp.async.wait_group 1;" ::: "memory");
        __syncthreads();
        if (kt + 2 < NK)
            load_stage(tid, kt + 2, sb, Ahi, Alo, Bhi, Blo, m0, n0);

        const uint32_t st = sb + (uint32_t)((kt % NSTG) * STAGE);
        #pragma unroll
        for (int ks = 0; ks < 2; ks++) {
            const uint32_t kadd = (uint32_t)(ks * 32);
            uint32_t ah[4][4], al[4][4], bh[4][2], bl[4][2];
            #pragma unroll
            for (int mt = 0; mt < 4; mt++) {
                uint32_t ad = st + a_off + (uint32_t)(mt * 16 * ROWB) + kadd;
                ldsm4(ah[mt], ad);
                ldsm4(al[mt], ad + ARR);
            }
            #pragma unroll
            for (int np = 0; np < 2; np++) {
                uint32_t bd = st + 2 * ARR + b_off + (uint32_t)(np * 16 * ROWB) + kadd;
                uint32_t r[4];
                ldsm4(r, bd);
                bh[np*2][0] = r[0]; bh[np*2][1] = r[1];
                bh[np*2+1][0] = r[2]; bh[np*2+1][1] = r[3];
                ldsm4(r, bd + ARR);
                bl[np*2][0] = r[0]; bl[np*2][1] = r[1];
                bl[np*2+1][0] = r[2]; bl[np*2+1][1] = r[3];
            }
            #pragma unroll
            for (int mt = 0; mt < 4; mt++)
                #pragma unroll
                for (int nt = 0; nt < 4; nt++) {
                    mma16816(acc[mt][nt], ah[mt], bh[nt]);
                    mma16816(acc[mt][nt], ah[mt], bl[nt]);
                    mma16816(acc[mt][nt], al[mt], bh[nt]);
                }
        }
        __syncthreads();
    }

    // Epilogue: direct register -> global stores (float2), + bias
    const int gid = lane >> 2;     // 0..7
    const int tig = lane & 3;      // 0..3
    #pragma unroll
    for (int mt = 0; mt < 4; mt++) {
        #pragma unroll
        for (int nt = 0; nt < 4; nt++) {
            int n = n0 + warpN + nt * 8 + tig * 2;
            float bx = bias[n], by = bias[n + 1];
            #pragma unroll
            for (int half = 0; half < 2; half++) {
                int m = m0 + warpM + mt * 16 + gid + half * 8;
                float2 v;
                v.x = acc[mt][nt][half * 2 + 0] + bx;
                v.y = acc[mt][nt][half * 2 + 1] + by;
                if (QKV_EP) {
                    int which = n >> 10;
                    int hh = (n >> 6) & 15;
                    int dd = n & 63;
                    int bb = m >> 11;
                    int tt = m & 2047;
                    float* dst = g_qkv
                        + (((size_t)which * BB + bb) * HH + hh) * (size_t)(TT * DD)
                        + (size_t)tt * DD + dd;
                    *(float2*)dst = v;
                } else {
                    *(float2*)(Cout + (size_t)m * N + n) = v;
                }
            }
        }
    }
}

// ---------------------------------------------------------------------------
// Flash attention fp32 (R1-proven core); epilogue writes bf16 hi/lo for proj.
// ---------------------------------------------------------------------------
__global__ void __launch_bounds__(64) attn_kernel()
{
    __shared__ float ks[4096];
    __shared__ float vs[4096];
    __shared__ float ss[4096];

    const int tid  = threadIdx.x;
    const int lane = tid & 31;
    const int bh   = blockIdx.y;
    const int q0   = blockIdx.x * 64;
    const int qi   = q0 + tid;
    const float NEG = -1e30f;

    const float* qp = g_qkv + ((size_t)bh * TT + qi) * DD;
    float qr[64];
    #pragma unroll
    for (int d4 = 0; d4 < 16; d4++) {
        float4 qv = *(const float4*)(qp + d4 * 4);
        qr[d4*4+0] = qv.x * 0.125f; qr[d4*4+1] = qv.y * 0.125f;
        qr[d4*4+2] = qv.z * 0.125f; qr[d4*4+3] = qv.w * 0.125f;
    }

    float acc[64];
    #pragma unroll
    for (int d = 0; d < 64; d++) acc[d] = 0.f;
    float m = NEG, l = 0.f;

    const float* kb = g_qkv + (size_t)BHTD     + (size_t)bh * TT * DD;
    const float* vb = g_qkv + (size_t)BHTD * 2 + (size_t)bh * TT * DD;
    float* my_ss = ss + tid * 64;

    for (int j0 = 0; j0 <= q0; j0 += 64) {
        const float4* k4 = (const float4*)(kb + (size_t)j0 * DD);
        const float4* v4 = (const float4*)(vb + (size_t)j0 * DD);
        #pragma unroll
        for (int i = 0; i < 16; i++) {
            ((float4*)ks)[tid + i * 64] = k4[tid + i * 64];
            ((float4*)vs)[tid + i * 64] = v4[tid + i * 64];
        }
        __syncthreads();

        float tm = NEG;
        #pragma unroll 4
        for (int j = 0; j < 64; j++) {
            const float4* kr = (const float4*)(ks + j * 64);
            float s = 0.f;
            #pragma unroll
            for (int dd = 0; dd < 16; dd++) {
                float4 kv = kr[dd];
                s += qr[dd*4+0] * kv.x; s += qr[dd*4+1] * kv.y;
                s += qr[dd*4+2] * kv.z; s += qr[dd*4+3] * kv.w;
            }
            if (j0 + j > qi) s = NEG;
            my_ss[j ^ lane] = s;
            tm = fmaxf(tm, s);
        }

        float mn   = fmaxf(m, tm);
        float corr = __expf(m - mn);
        m = mn;
        float lsum = 0.f;
        #pragma unroll 8
        for (int j = 0; j < 64; j++) {
            float p = __expf(my_ss[j ^ lane] - mn);
            my_ss[j ^ lane] = p;
            lsum += p;
        }
        l = l * corr + lsum;
        #pragma unroll
        for (int d = 0; d < 64; d++) acc[d] *= corr;

        #pragma unroll 2
        for (int j = 0; j < 64; j++) {
            float p = my_ss[j ^ lane];
            const float4* vr = (const float4*)(vs + j * 64);
            #pragma unroll
            for (int dd = 0; dd < 16; dd++) {
                float4 vv = vr[dd];
                acc[dd*4+0] += p * vv.x; acc[dd*4+1] += p * vv.y;
                acc[dd*4+2] += p * vv.z; acc[dd*4+3] += p * vv.w;
            }
        }
        __syncthreads();
    }

    float inv = 1.f / l;
    size_t ro = ((size_t)(bh >> 4) * TT + qi) * CC + (size_t)(bh & 15) * DD;
    #pragma unroll
    for (int d2 = 0; d2 < 32; d2++) {
        float v0 = acc[d2*2]   * inv;
        float v1 = acc[d2*2+1] * inv;
        __nv_bfloat16 h0 = __float2bfloat16_rn(v0);
        __nv_bfloat16 h1 = __float2bfloat16_rn(v1);
        __nv_bfloat16 l0 = __float2bfloat16_rn(v0 - __bfloat162float(h0));
        __nv_bfloat16 l1 = __float2bfloat16_rn(v1 - __bfloat162float(h1));
        *(__nv_bfloat162*)(g_att_hi + ro + d2*2) = __halves2bfloat162(h0, h1);
        *(__nv_bfloat162*)(g_att_lo + ro + d2*2) = __halves2bfloat162(l0, l1);
    }
}

// ---------------------------------------------------------------------------
extern "C" void kernel_launch(void* const* d_in, const int* in_sizes, int n_in,
                              void* d_out, int out_size)
{
    const float* x      = (const float*)d_in[0];
    const float* w_attn = (const float*)d_in[1];
    const float* b_attn = (const float*)d_in[2];
    const float* w_proj = (const float*)d_in[3];
    const float* b_proj = (const float*)d_in[4];
    float* out = (float*)d_out;

    __nv_bfloat16 *xh, *xl, *wqh, *wql, *wph, *wpl, *ah, *al;
    cudaGetSymbolAddress((void**)&xh,  g_x_hi);
    cudaGetSymbolAddress((void**)&xl,  g_x_lo);
    cudaGetSymbolAddress((void**)&wqh, g_wq_hi);
    cudaGetSymbolAddress((void**)&wql, g_wq_lo);
    cudaGetSymbolAddress((void**)&wph, g_wp_hi);
    cudaGetSymbolAddress((void**)&wpl, g_wp_lo);
    cudaGetSymbolAddress((void**)&ah,  g_att_hi);
    cudaGetSymbolAddress((void**)&al,  g_att_lo);

    cudaFuncSetAttribute(gemm_mma<true>,  cudaFuncAttributeMaxDynamicSharedMemorySize, GEMM_SMEM);
    cudaFuncSetAttribute(gemm_mma<false>, cudaFuncAttributeMaxDynamicSharedMemorySize, GEMM_SMEM);

    // Prepass: splits + transposed/split weights
    split_kernel<<<4096, 256>>>(x, xh, xl);
    tsplit_kernel<<<dim3(96, 32), dim3(32, 32)>>>(w_attn, wqh, wql, 3072, 1024);
    tsplit_kernel<<<dim3(32, 32), dim3(32, 32)>>>(w_proj, wph, wpl, 1024, 1024);

    // 1) QKV GEMM (HMMA) -> g_qkv [3,B,H,T,D]
    gemm_mma<true><<<dim3(24, 32), 256, GEMM_SMEM>>>(xh, xl, wqh, wql, b_attn, nullptr, 3072);

    // 2) Causal flash attention -> g_att_hi/lo (bf16 split)
    attn_kernel<<<dim3(TT / 64, BB * HH), 64>>>();

    // 3) Output projection (HMMA) -> d_out
    gemm_mma<false><<<dim3(8, 32), 256, GEMM_SMEM>>>(ah, al, wph, wpl, b_proj, out, 1024);
}

// round 4
// speedup vs baseline: 5.7605x; 2.4070x over previous
#include <cuda_runtime.h>
#include <cuda_bf16.h>
#include <cstdint>

#define BB 2
#define TT 2048
#define CC 1024
#define HH 16
#define DD 64
#define BHTD (BB*HH*TT*DD)   // 4,194,304

// ---------------------------------------------------------------------------
// Scratch (__device__ globals; allocation-free rule)
// ---------------------------------------------------------------------------
__device__ __align__(16) __nv_bfloat16 g_x_hi[4096ll * 1024];
__device__ __align__(16) __nv_bfloat16 g_x_lo[4096ll * 1024];
__device__ __align__(16) __nv_bfloat16 g_wq_hi[3072ll * 1024];       // w_attn^T [N,K]
__device__ __align__(16) __nv_bfloat16 g_wq_lo[3072ll * 1024];
__device__ __align__(16) __nv_bfloat16 g_wp_hi[1024ll * 1024];       // w_proj^T [N,K]
__device__ __align__(16) __nv_bfloat16 g_wp_lo[1024ll * 1024];
__device__ __align__(16) __nv_bfloat16 g_att_hi[4096ll * 1024];      // attn out split [M,K]
__device__ __align__(16) __nv_bfloat16 g_att_lo[4096ll * 1024];
// QKV split outputs, [B*H, T, D]
__device__ __align__(16) __nv_bfloat16 g_q_hi[BHTD];
__device__ __align__(16) __nv_bfloat16 g_q_lo[BHTD];
__device__ __align__(16) __nv_bfloat16 g_k_hi[BHTD];
__device__ __align__(16) __nv_bfloat16 g_k_lo[BHTD];
__device__ __align__(16) __nv_bfloat16 g_v_hi[BHTD];
__device__ __align__(16) __nv_bfloat16 g_v_lo[BHTD];

// ---------------------------------------------------------------------------
// Helpers
// ---------------------------------------------------------------------------
__device__ __forceinline__ uint32_t smem_u32(const void* p) {
    uint32_t a;
    asm("{ .reg .u64 t; cvta.to.shared.u64 t, %1; cvt.u32.u64 %0, t; }" : "=r"(a) : "l"(p));
    return a;
}
__device__ __forceinline__ void cp_async16(uint32_t dst, const void* src) {
    asm volatile("cp.async.cg.shared.global [%0], [%1], 16;" :: "r"(dst), "l"(src));
}
#define CP_COMMIT() asm volatile("cp.async.commit_group;" ::: "memory")

__device__ __forceinline__ void ldsm4(uint32_t* r, uint32_t addr) {
    asm volatile("ldmatrix.sync.aligned.m8n8.x4.shared.b16 {%0,%1,%2,%3}, [%4];"
        : "=r"(r[0]), "=r"(r[1]), "=r"(r[2]), "=r"(r[3]) : "r"(addr));
}
__device__ __forceinline__ void ldsm4t(uint32_t* r, uint32_t addr) {
    asm volatile("ldmatrix.sync.aligned.m8n8.x4.trans.shared.b16 {%0,%1,%2,%3}, [%4];"
        : "=r"(r[0]), "=r"(r[1]), "=r"(r[2]), "=r"(r[3]) : "r"(addr));
}
__device__ __forceinline__ void mma16816(float* d, const uint32_t* a, const uint32_t* b) {
    asm volatile("mma.sync.aligned.m16n8k16.row.col.f32.bf16.bf16.f32 "
        "{%0,%1,%2,%3}, {%4,%5,%6,%7}, {%8,%9}, {%0,%1,%2,%3};"
        : "+f"(d[0]), "+f"(d[1]), "+f"(d[2]), "+f"(d[3])
        : "r"(a[0]), "r"(a[1]), "r"(a[2]), "r"(a[3]), "r"(b[0]), "r"(b[1]));
}
__device__ __forceinline__ void split2(float x, float y, uint32_t& hi, uint32_t& lo) {
    __nv_bfloat16 hx = __float2bfloat16_rn(x), hy = __float2bfloat16_rn(y);
    __nv_bfloat16 lx = __float2bfloat16_rn(x - __bfloat162float(hx));
    __nv_bfloat16 ly = __float2bfloat16_rn(y - __bfloat162float(hy));
    __nv_bfloat162 h2 = __halves2bfloat162(hx, hy);
    __nv_bfloat162 l2 = __halves2bfloat162(lx, ly);
    hi = *reinterpret_cast<uint32_t*>(&h2);
    lo = *reinterpret_cast<uint32_t*>(&l2);
}

// ---------------------------------------------------------------------------
// Prepass: split fp32 -> (hi, lo) bf16
// ---------------------------------------------------------------------------
__global__ void split_kernel(const float* __restrict__ X,
                             __nv_bfloat16* __restrict__ hi,
                             __nv_bfloat16* __restrict__ lo)
{
    int i = blockIdx.x * blockDim.x + threadIdx.x;
    float4 v = ((const float4*)X)[i];
    uint32_t h0, l0, h1, l1;
    split2(v.x, v.y, h0, l0);
    split2(v.z, v.w, h1, l1);
    *(uint32_t*)(hi + (size_t)i * 4)     = h0;
    *(uint32_t*)(hi + (size_t)i * 4 + 2) = h1;
    *(uint32_t*)(lo + (size_t)i * 4)     = l0;
    *(uint32_t*)(lo + (size_t)i * 4 + 2) = l1;
}

__global__ void tsplit_kernel(const float* __restrict__ W,
                              __nv_bfloat16* __restrict__ Thi,
                              __nv_bfloat16* __restrict__ Tlo,
                              int Ncols, int Krows)
{
    __shared__ float ts[32][33];
    int n0 = blockIdx.x * 32, k0 = blockIdx.y * 32;
    int tx = threadIdx.x, ty = threadIdx.y;
    ts[ty][tx] = W[(size_t)(k0 + ty) * Ncols + n0 + tx];
    __syncthreads();
    float v = ts[tx][ty];
    __nv_bfloat16 h = __float2bfloat16_rn(v);
    size_t o = (size_t)(n0 + ty) * Krows + k0 + tx;
    Thi[o] = h;
    Tlo[o] = __float2bfloat16_rn(v - __bfloat162float(h));
}

// ---------------------------------------------------------------------------
// bf16x3 GEMM via mma.sync (same as R3). QKV_EP: write split bf16 q/k/v.
// ---------------------------------------------------------------------------
#define ROWB 80
#define ARR  (128 * ROWB)
#define STAGE (4 * ARR)
#define NSTG 3
#define GEMM_SMEM (NSTG * STAGE)
#define NK 32

__device__ __forceinline__ void load_stage(
    int tid, int kt, uint32_t sbase,
    const __nv_bfloat16* Ahi, const __nv_bfloat16* Alo,
    const __nv_bfloat16* Bhi, const __nv_bfloat16* Blo,
    int m0, int n0)
{
    const uint32_t st = sbase + (uint32_t)((kt % NSTG) * STAGE);
    const int k0 = kt * 32;
    #pragma unroll
    for (int i = 0; i < 2; i++) {
        int chunk = tid + i * 256;
        int r = chunk >> 2, c = chunk & 3;
        uint32_t d = (uint32_t)(r * ROWB + c * 16);
        size_t goA = (size_t)(m0 + r) * 1024 + k0 + c * 8;
        size_t goB = (size_t)(n0 + r) * 1024 + k0 + c * 8;
        cp_async16(st +           d, Ahi + goA);
        cp_async16(st + ARR     + d, Alo + goA);
        cp_async16(st + 2 * ARR + d, Bhi + goB);
        cp_async16(st + 3 * ARR + d, Blo + goB);
    }
    CP_COMMIT();
}

template<bool QKV_EP>
__global__ void __launch_bounds__(256) gemm_mma(
    const __nv_bfloat16* __restrict__ Ahi, const __nv_bfloat16* __restrict__ Alo,
    const __nv_bfloat16* __restrict__ Bhi, const __nv_bfloat16* __restrict__ Blo,
    const float* __restrict__ bias, float* __restrict__ Cout, int N)
{
    extern __shared__ __align__(128) char smem[];
    const uint32_t sb = smem_u32(smem);
    const int tid  = threadIdx.x;
    const int wid  = tid >> 5;
    const int lane = tid & 31;
    const int m0 = blockIdx.y * 128;
    const int n0 = blockIdx.x * 128;
    const int warpM = (wid >> 2) * 64;
    const int warpN = (wid & 3) * 32;

    float acc[4][4][4];
    #pragma unroll
    for (int i = 0; i < 4; i++)
        #pragma unroll
        for (int j = 0; j < 4; j++)
            #pragma unroll
            for (int e = 0; e < 4; e++) acc[i][j][e] = 0.f;

    const uint32_t a_off = (uint32_t)((warpM + (lane & 15)) * ROWB + (lane >> 4) * 16);
    const int brow = (lane & 7) + ((lane >> 4) << 3);
    const uint32_t b_off = (uint32_t)((warpN + brow) * ROWB + ((lane >> 3) & 1) * 16);

    load_stage(tid, 0, sb, Ahi, Alo, Bhi, Blo, m0, n0);
    load_stage(tid, 1, sb, Ahi, Alo, Bhi, Blo, m0, n0);

    for (int kt = 0; kt < NK; kt++) {
        asm volatile("cp.async.wait_group 1;" ::: "memory");
        __syncthreads();
        if (kt + 2 < NK)
            load_stage(tid, kt + 2, sb, Ahi, Alo, Bhi, Blo, m0, n0);

        const uint32_t st = sb + (uint32_t)((kt % NSTG) * STAGE);
        #pragma unroll
        for (int ks = 0; ks < 2; ks++) {
            const uint32_t kadd = (uint32_t)(ks * 32);
            uint32_t ah[4][4], al[4][4], bh[4][2], bl[4][2];
            #pragma unroll
            for (int mt = 0; mt < 4; mt++) {
                uint32_t ad = st + a_off + (uint32_t)(mt * 16 * ROWB) + kadd;
                ldsm4(ah[mt], ad);
                ldsm4(al[mt], ad + ARR);
            }
            #pragma unroll
            for (int np = 0; np < 2; np++) {
                uint32_t bd = st + 2 * ARR + b_off + (uint32_t)(np * 16 * ROWB) + kadd;
                uint32_t r[4];
                ldsm4(r, bd);
                bh[np*2][0] = r[0]; bh[np*2][1] = r[1];
                bh[np*2+1][0] = r[2]; bh[np*2+1][1] = r[3];
                ldsm4(r, bd + ARR);
                bl[np*2][0] = r[0]; bl[np*2][1] = r[1];
                bl[np*2+1][0] = r[2]; bl[np*2+1][1] = r[3];
            }
            #pragma unroll
            for (int mt = 0; mt < 4; mt++)
                #pragma unroll
                for (int nt = 0; nt < 4; nt++) {
                    mma16816(acc[mt][nt], ah[mt], bh[nt]);
                    mma16816(acc[mt][nt], ah[mt], bl[nt]);
                    mma16816(acc[mt][nt], al[mt], bh[nt]);
                }
        }
        __syncthreads();
    }

    const int gid = lane >> 2;
    const int tig = lane & 3;
    #pragma unroll
    for (int mt = 0; mt < 4; mt++) {
        #pragma unroll
        for (int nt = 0; nt < 4; nt++) {
            int n = n0 + warpN + nt * 8 + tig * 2;
            float bx = bias[n], by = bias[n + 1];
            #pragma unroll
            for (int half = 0; half < 2; half++) {
                int m = m0 + warpM + mt * 16 + gid + half * 8;
                float vx = acc[mt][nt][half * 2 + 0] + bx;
                float vy = acc[mt][nt][half * 2 + 1] + by;
                if (QKV_EP) {
                    int which = n >> 10;
                    int hh = (n >> 6) & 15;
                    int dd = n & 63;
                    int bb = m >> 11;
                    int tt = m & 2047;
                    if (which == 0) { vx *= 0.125f; vy *= 0.125f; }
                    uint32_t hi, lo;
                    split2(vx, vy, hi, lo);
                    size_t off = (((size_t)bb * HH + hh) * TT + tt) * DD + dd;
                    __nv_bfloat16* ph = (which == 0) ? g_q_hi : (which == 1) ? g_k_hi : g_v_hi;
                    __nv_bfloat16* pl = (which == 0) ? g_q_lo : (which == 1) ? g_k_lo : g_v_lo;
                    *(uint32_t*)(ph + off) = hi;
                    *(uint32_t*)(pl + off) = lo;
                } else {
                    float2 v; v.x = vx; v.y = vy;
                    *(float2*)(Cout + (size_t)m * N + n) = v;
                }
            }
        }
    }
}

// ---------------------------------------------------------------------------
// Tensor-core flash attention (split-bf16 QK^T and PV).
// Block: 128 threads (4 warps x 16 query rows = 64 queries). K/V tiles of 64
// keys, double-buffered cp.async. Online softmax in registers.
// ---------------------------------------------------------------------------
#define AT_ROWB 144
#define AT_TILE (64 * AT_ROWB)          // 9216 B
#define ATT_SMEM (2 * AT_TILE + 2 * 4 * AT_TILE)   // 92160 B

__global__ void __launch_bounds__(128) attn_mma()
{
    extern __shared__ __align__(128) char smem[];
    const uint32_t sb = smem_u32(smem);
    const int tid  = threadIdx.x;
    const int wid  = tid >> 5;
    const int lane = tid & 31;
    const int bh = blockIdx.y;
    const int q0 = blockIdx.x * 64;
    const int warpM = wid * 16;
    const size_t bhoff = (size_t)bh * TT * DD;

    const uint32_t kvbase0 = sb + 2 * AT_TILE;

    // --- load Q tile (hi+lo) ---
    {
        const __nv_bfloat16* Qh = g_q_hi + bhoff + (size_t)q0 * DD;
        const __nv_bfloat16* Ql = g_q_lo + bhoff + (size_t)q0 * DD;
        for (int i = tid; i < 512; i += 128) {
            int r = i >> 3, c = i & 7;
            uint32_t d = (uint32_t)(r * AT_ROWB + c * 16);
            size_t go = (size_t)r * DD + c * 8;
            cp_async16(sb + d,          Qh + go);
            cp_async16(sb + AT_TILE + d, Ql + go);
        }
        CP_COMMIT();
    }

    const int njt = q0 / 64 + 1;

    // --- load K/V tile 0 ---
    {
        const __nv_bfloat16* Kh = g_k_hi + bhoff;
        const __nv_bfloat16* Kl = g_k_lo + bhoff;
        const __nv_bfloat16* Vh = g_v_hi + bhoff;
        const __nv_bfloat16* Vl = g_v_lo + bhoff;
        for (int i = tid; i < 512; i += 128) {
            int r = i >> 3, c = i & 7;
            uint32_t d = (uint32_t)(r * AT_ROWB + c * 16);
            size_t go = (size_t)r * DD + c * 8;
            cp_async16(kvbase0 + d,               Kh + go);
            cp_async16(kvbase0 + AT_TILE + d,     Kl + go);
            cp_async16(kvbase0 + 2 * AT_TILE + d, Vh + go);
            cp_async16(kvbase0 + 3 * AT_TILE + d, Vl + go);
        }
        CP_COMMIT();
    }

    // Q fragments
    asm volatile("cp.async.wait_group 1;" ::: "memory");
    __syncthreads();
    uint32_t qh[4][4], ql[4][4];
    const uint32_t a_off = (uint32_t)((warpM + (lane & 15)) * AT_ROWB + (lane >> 4) * 16);
    #pragma unroll
    for (int ks = 0; ks < 4; ks++) {
        ldsm4(qh[ks], sb + a_off + ks * 32);
        ldsm4(ql[ks], sb + AT_TILE + a_off + ks * 32);
    }

    float o[8][4];
    #pragma unroll
    for (int i = 0; i < 8; i++)
        #pragma unroll
        for (int e = 0; e < 4; e++) o[i][e] = 0.f;
    float m0 = -1e30f, m1 = -1e30f, l0 = 0.f, l1 = 0.f;

    const int brow = (lane & 7) + ((lane >> 4) << 3);
    const uint32_t b_off = (uint32_t)(brow * AT_ROWB + ((lane >> 3) & 1) * 16);
    const int vrow = (lane & 7) + ((lane >> 3) & 1) * 8;
    const uint32_t v_off = (uint32_t)(vrow * AT_ROWB + (lane >> 4) * 16);

    for (int jt = 0; jt < njt; jt++) {
        // prefetch next K/V tile
        if (jt + 1 < njt) {
            uint32_t nb = sb + 2 * AT_TILE + (uint32_t)(((jt + 1) & 1) * 4 * AT_TILE);
            size_t jo = (size_t)(jt + 1) * 64 * DD;
            const __nv_bfloat16* Kh = g_k_hi + bhoff + jo;
            const __nv_bfloat16* Kl = g_k_lo + bhoff + jo;
            const __nv_bfloat16* Vh = g_v_hi + bhoff + jo;
            const __nv_bfloat16* Vl = g_v_lo + bhoff + jo;
            for (int i = tid; i < 512; i += 128) {
                int r = i >> 3, c = i & 7;
                uint32_t d = (uint32_t)(r * AT_ROWB + c * 16);
                size_t go = (size_t)r * DD + c * 8;
                cp_async16(nb + d,               Kh + go);
                cp_async16(nb + AT_TILE + d,     Kl + go);
                cp_async16(nb + 2 * AT_TILE + d, Vh + go);
                cp_async16(nb + 3 * AT_TILE + d, Vl + go);
            }
            CP_COMMIT();
            asm volatile("cp.async.wait_group 1;" ::: "memory");
        } else {
            asm volatile("cp.async.wait_group 0;" ::: "memory");
        }
        __syncthreads();

        const uint32_t kb = sb + 2 * AT_TILE + (uint32_t)((jt & 1) * 4 * AT_TILE);

        // ---- S = Q K^T (3-term split) ----
        float s[8][4];
        #pragma unroll
        for (int i = 0; i < 8; i++)
            #pragma unroll
            for (int e = 0; e < 4; e++) s[i][e] = 0.f;

        #pragma unroll
        for (int ks = 0; ks < 4; ks++) {
            #pragma unroll
            for (int np = 0; np < 4; np++) {
                uint32_t rh[4], rl[4];
                uint32_t bd = kb + b_off + (uint32_t)(np * 16 * AT_ROWB) + ks * 32;
                ldsm4(rh, bd);
                ldsm4(rl, bd + AT_TILE);
                uint32_t bh0[2] = {rh[0], rh[1]}, bh1[2] = {rh[2], rh[3]};
                uint32_t bl0[2] = {rl[0], rl[1]}, bl1[2] = {rl[2], rl[3]};
                mma16816(s[np*2],   qh[ks], bh0);
                mma16816(s[np*2],   ql[ks], bh0);
                mma16816(s[np*2],   qh[ks], bl0);
                mma16816(s[np*2+1], qh[ks], bh1);
                mma16816(s[np*2+1], ql[ks], bh1);
                mma16816(s[np*2+1], qh[ks], bl1);
            }
        }

        // causal mask (diagonal tile only)
        if (jt == njt - 1) {
            int r0 = warpM + (lane >> 2);
            #pragma unroll
            for (int nt = 0; nt < 8; nt++) {
                int c0 = nt * 8 + (lane & 3) * 2;
                #pragma unroll
                for (int e = 0; e < 4; e++) {
                    int row = r0 + (e >> 1) * 8;
                    int col = c0 + (e & 1);
                    if (col > row) s[nt][e] = -1e30f;
                }
            }
        }

        // ---- online softmax ----
        float tm0 = -1e30f, tm1 = -1e30f;
        #pragma unroll
        for (int nt = 0; nt < 8; nt++) {
            tm0 = fmaxf(tm0, fmaxf(s[nt][0], s[nt][1]));
            tm1 = fmaxf(tm1, fmaxf(s[nt][2], s[nt][3]));
        }
        tm0 = fmaxf(tm0, __shfl_xor_sync(0xffffffff, tm0, 1));
        tm0 = fmaxf(tm0, __shfl_xor_sync(0xffffffff, tm0, 2));
        tm1 = fmaxf(tm1, __shfl_xor_sync(0xffffffff, tm1, 1));
        tm1 = fmaxf(tm1, __shfl_xor_sync(0xffffffff, tm1, 2));

        float nm0 = fmaxf(m0, tm0), nm1 = fmaxf(m1, tm1);
        float c0s = __expf(m0 - nm0), c1s = __expf(m1 - nm1);
        m0 = nm0; m1 = nm1;

        float ls0 = 0.f, ls1 = 0.f;
        #pragma unroll
        for (int nt = 0; nt < 8; nt++) {
            s[nt][0] = __expf(s[nt][0] - nm0); ls0 += s[nt][0];
            s[nt][1] = __expf(s[nt][1] - nm0); ls0 += s[nt][1];
            s[nt][2] = __expf(s[nt][2] - nm1); ls1 += s[nt][2];
            s[nt][3] = __expf(s[nt][3] - nm1); ls1 += s[nt][3];
        }
        ls0 += __shfl_xor_sync(0xffffffff, ls0, 1);
        ls0 += __shfl_xor_sync(0xffffffff, ls0, 2);
        ls1 += __shfl_xor_sync(0xffffffff, ls1, 1);
        ls1 += __shfl_xor_sync(0xffffffff, ls1, 2);
        l0 = l0 * c0s + ls0;
        l1 = l1 * c1s + ls1;

        #pragma unroll
        for (int dt = 0; dt < 8; dt++) {
            o[dt][0] *= c0s; o[dt][1] *= c0s;
            o[dt][2] *= c1s; o[dt][3] *= c1s;
        }

        // ---- P -> bf16 A fragments (hi/lo) ----
        uint32_t ph[4][4], pl[4][4];
        #pragma unroll
        for (int ksv = 0; ksv < 4; ksv++) {
            split2(s[2*ksv][0],   s[2*ksv][1],   ph[ksv][0], pl[ksv][0]);
            split2(s[2*ksv][2],   s[2*ksv][3],   ph[ksv][1], pl[ksv][1]);
            split2(s[2*ksv+1][0], s[2*ksv+1][1], ph[ksv][2], pl[ksv][2]);
            split2(s[2*ksv+1][2], s[2*ksv+1][3], ph[ksv][3], pl[ksv][3]);
        }

        // ---- O += P V (3-term split) ----
        const uint32_t vb = kb + 2 * AT_TILE;
        #pragma unroll
        for (int ksv = 0; ksv < 4; ksv++) {
            #pragma unroll
            for (int dg = 0; dg < 4; dg++) {
                uint32_t rh[4], rl[4];
                uint32_t vd = vb + v_off + (uint32_t)(ksv * 16 * AT_ROWB) + dg * 32;
                ldsm4t(rh, vd);
                ldsm4t(rl, vd + AT_TILE);
                uint32_t vh0[2] = {rh[0], rh[1]}, vh1[2] = {rh[2], rh[3]};
                uint32_t vl0[2] = {rl[0], rl[1]}, vl1[2] = {rl[2], rl[3]};
                mma16816(o[dg*2],   ph[ksv], vh0);
                mma16816(o[dg*2],   pl[ksv], vh0);
                mma16816(o[dg*2],   ph[ksv], vl0);
                mma16816(o[dg*2+1], ph[ksv], vh1);
                mma16816(o[dg*2+1], pl[ksv], vh1);
                mma16816(o[dg*2+1], ph[ksv], vl1);
            }
        }
        __syncthreads();
    }

    // ---- epilogue: normalize, split, store to g_att_hi/lo [B*T, C] ----
    float inv0 = 1.f / l0, inv1 = 1.f / l1;
    int qi = q0 + warpM + (lane >> 2);
    size_t ro0 = ((size_t)(bh >> 4) * TT + qi) * CC + (size_t)(bh & 15) * DD;
    size_t ro1 = ro0 + (size_t)8 * CC;
    #pragma unroll
    for (int dt = 0; dt < 8; dt++) {
        int col = dt * 8 + (lane & 3) * 2;
        uint32_t hi, lo;
        split2(o[dt][0] * inv0, o[dt][1] * inv0, hi, lo);
        *(uint32_t*)(g_att_hi + ro0 + col) = hi;
        *(uint32_t*)(g_att_lo + ro0 + col) = lo;
        split2(o[dt][2] * inv1, o[dt][3] * inv1, hi, lo);
        *(uint32_t*)(g_att_hi + ro1 + col) = hi;
        *(uint32_t*)(g_att_lo + ro1 + col) = lo;
    }
}

// ---------------------------------------------------------------------------
extern "C" void kernel_launch(void* const* d_in, const int* in_sizes, int n_in,
                              void* d_out, int out_size)
{
    const float* x      = (const float*)d_in[0];
    const float* w_attn = (const float*)d_in[1];
    const float* b_attn = (const float*)d_in[2];
    const float* w_proj = (const float*)d_in[3];
    const float* b_proj = (const float*)d_in[4];
    float* out = (float*)d_out;

    __nv_bfloat16 *xh, *xl, *wqh, *wql, *wph, *wpl, *ah, *al;
    cudaGetSymbolAddress((void**)&xh,  g_x_hi);
    cudaGetSymbolAddress((void**)&xl,  g_x_lo);
    cudaGetSymbolAddress((void**)&wqh, g_wq_hi);
    cudaGetSymbolAddress((void**)&wql, g_wq_lo);
    cudaGetSymbolAddress((void**)&wph, g_wp_hi);
    cudaGetSymbolAddress((void**)&wpl, g_wp_lo);
    cudaGetSymbolAddress((void**)&ah,  g_att_hi);
    cudaGetSymbolAddress((void**)&al,  g_att_lo);

    cudaFuncSetAttribute(gemm_mma<true>,  cudaFuncAttributeMaxDynamicSharedMemorySize, GEMM_SMEM);
    cudaFuncSetAttribute(gemm_mma<false>, cudaFuncAttributeMaxDynamicSharedMemorySize, GEMM_SMEM);
    cudaFuncSetAttribute(attn_mma, cudaFuncAttributeMaxDynamicSharedMemorySize, ATT_SMEM);

    split_kernel<<<4096, 256>>>(x, xh, xl);
    tsplit_kernel<<<dim3(96, 32), dim3(32, 32)>>>(w_attn, wqh, wql, 3072, 1024);
    tsplit_kernel<<<dim3(32, 32), dim3(32, 32)>>>(w_proj, wph, wpl, 1024, 1024);

    // 1) QKV GEMM -> split bf16 q/k/v [B,H,T,D]
    gemm_mma<true><<<dim3(24, 32), 256, GEMM_SMEM>>>(xh, xl, wqh, wql, b_attn, nullptr, 3072);

    // 2) Tensor-core causal flash attention -> g_att_hi/lo
    attn_mma<<<dim3(TT / 64, BB * HH), 128, ATT_SMEM>>>();

    // 3) Output projection -> d_out
    gemm_mma<false><<<dim3(8, 32), 256, GEMM_SMEM>>>(ah, al, wph, wpl, b_proj, out, 1024);
}

// round 5
// speedup vs baseline: 6.8899x; 1.1961x over previous
#include <cuda_runtime.h>
#include <cuda_bf16.h>
#include <cstdint>

#define BB 2
#define TT 2048
#define CC 1024
#define HH 16
#define DD 64
#define BHTD (BB*HH*TT*DD)   // 4,194,304

// ---------------------------------------------------------------------------
// Scratch (__device__ globals; allocation-free rule)
// ---------------------------------------------------------------------------
__device__ __align__(16) __nv_bfloat16 g_x_hi[4096ll * 1024];
__device__ __align__(16) __nv_bfloat16 g_x_lo[4096ll * 1024];
__device__ __align__(16) __nv_bfloat16 g_wq_hi[3072ll * 1024];       // w_attn^T [N,K]
__device__ __align__(16) __nv_bfloat16 g_wq_lo[3072ll * 1024];
__device__ __align__(16) __nv_bfloat16 g_wp_hi[1024ll * 1024];       // w_proj^T [N,K]
__device__ __align__(16) __nv_bfloat16 g_wp_lo[1024ll * 1024];
__device__ __align__(16) __nv_bfloat16 g_att_hi[4096ll * 1024];      // attn out split [M,K]
__device__ __align__(16) __nv_bfloat16 g_att_lo[4096ll * 1024];
// QKV split outputs, [B*H, T, D]
__device__ __align__(16) __nv_bfloat16 g_q_hi[BHTD];
__device__ __align__(16) __nv_bfloat16 g_q_lo[BHTD];
__device__ __align__(16) __nv_bfloat16 g_k_hi[BHTD];
__device__ __align__(16) __nv_bfloat16 g_k_lo[BHTD];
__device__ __align__(16) __nv_bfloat16 g_v_hi[BHTD];
__device__ __align__(16) __nv_bfloat16 g_v_lo[BHTD];

// ---------------------------------------------------------------------------
// Helpers
// ---------------------------------------------------------------------------
__device__ __forceinline__ uint32_t smem_u32(const void* p) {
    uint32_t a;
    asm("{ .reg .u64 t; cvta.to.shared.u64 t, %1; cvt.u32.u64 %0, t; }" : "=r"(a) : "l"(p));
    return a;
}
__device__ __forceinline__ void cp_async16(uint32_t dst, const void* src) {
    asm volatile("cp.async.cg.shared.global [%0], [%1], 16;" :: "r"(dst), "l"(src));
}
#define CP_COMMIT() asm volatile("cp.async.commit_group;" ::: "memory")
__device__ __forceinline__ uint32_t sw64(uint32_t off) {      // SW64 XOR swizzle
    return off ^ ((off >> 3) & 0x30);
}

__device__ __forceinline__ void ldsm4(uint32_t* r, uint32_t addr) {
    asm volatile("ldmatrix.sync.aligned.m8n8.x4.shared.b16 {%0,%1,%2,%3}, [%4];"
        : "=r"(r[0]), "=r"(r[1]), "=r"(r[2]), "=r"(r[3]) : "r"(addr));
}
__device__ __forceinline__ void ldsm4t(uint32_t* r, uint32_t addr) {
    asm volatile("ldmatrix.sync.aligned.m8n8.x4.trans.shared.b16 {%0,%1,%2,%3}, [%4];"
        : "=r"(r[0]), "=r"(r[1]), "=r"(r[2]), "=r"(r[3]) : "r"(addr));
}
__device__ __forceinline__ void mma16816(float* d, const uint32_t* a, const uint32_t* b) {
    asm volatile("mma.sync.aligned.m16n8k16.row.col.f32.bf16.bf16.f32 "
        "{%0,%1,%2,%3}, {%4,%5,%6,%7}, {%8,%9}, {%0,%1,%2,%3};"
        : "+f"(d[0]), "+f"(d[1]), "+f"(d[2]), "+f"(d[3])
        : "r"(a[0]), "r"(a[1]), "r"(a[2]), "r"(a[3]), "r"(b[0]), "r"(b[1]));
}
__device__ __forceinline__ void split2(float x, float y, uint32_t& hi, uint32_t& lo) {
    __nv_bfloat16 hx = __float2bfloat16_rn(x), hy = __float2bfloat16_rn(y);
    __nv_bfloat16 lx = __float2bfloat16_rn(x - __bfloat162float(hx));
    __nv_bfloat16 ly = __float2bfloat16_rn(y - __bfloat162float(hy));
    __nv_bfloat162 h2 = __halves2bfloat162(hx, hy);
    __nv_bfloat162 l2 = __halves2bfloat162(lx, ly);
    hi = *reinterpret_cast<uint32_t*>(&h2);
    lo = *reinterpret_cast<uint32_t*>(&l2);
}

// ---------------------------------------------------------------------------
// Prepass kernels
// ---------------------------------------------------------------------------
__global__ void split_kernel(const float* __restrict__ X,
                             __nv_bfloat16* __restrict__ hi,
                             __nv_bfloat16* __restrict__ lo)
{
    int i = blockIdx.x * blockDim.x + threadIdx.x;
    float4 v = ((const float4*)X)[i];
    uint32_t h0, l0, h1, l1;
    split2(v.x, v.y, h0, l0);
    split2(v.z, v.w, h1, l1);
    *(uint32_t*)(hi + (size_t)i * 4)     = h0;
    *(uint32_t*)(hi + (size_t)i * 4 + 2) = h1;
    *(uint32_t*)(lo + (size_t)i * 4)     = l0;
    *(uint32_t*)(lo + (size_t)i * 4 + 2) = l1;
}

__global__ void tsplit_kernel(const float* __restrict__ W,
                              __nv_bfloat16* __restrict__ Thi,
                              __nv_bfloat16* __restrict__ Tlo,
                              int Ncols, int Krows)
{
    __shared__ float ts[32][33];
    int n0 = blockIdx.x * 32, k0 = blockIdx.y * 32;
    int tx = threadIdx.x, ty = threadIdx.y;
    ts[ty][tx] = W[(size_t)(k0 + ty) * Ncols + n0 + tx];
    __syncthreads();
    float v = ts[tx][ty];
    __nv_bfloat16 h = __float2bfloat16_rn(v);
    size_t o = (size_t)(n0 + ty) * Krows + k0 + tx;
    Thi[o] = h;
    Tlo[o] = __float2bfloat16_rn(v - __bfloat162float(h));
}

// ---------------------------------------------------------------------------
// bf16x3 GEMM via mma.sync. SW64-swizzled smem (32KB/stage, 3 stages = 96KB
// -> 2 CTAs/SM). Term-major MMA order (no accumulator RAW chains).
// ---------------------------------------------------------------------------
#define ARR   8192                  // 128 rows x 64B
#define STAGE (4 * ARR)             // Ahi,Alo,Bhi,Blo = 32768
#define NSTG 3
#define GEMM_SMEM (NSTG * STAGE)    // 98304
#define NK 32

__device__ __forceinline__ void load_stage(
    int tid, int kt, uint32_t sbase,
    const __nv_bfloat16* Ahi, const __nv_bfloat16* Alo,
    const __nv_bfloat16* Bhi, const __nv_bfloat16* Blo,
    int m0, int n0)
{
    const uint32_t st = sbase + (uint32_t)((kt % NSTG) * STAGE);
    const int k0 = kt * 32;
    #pragma unroll
    for (int i = 0; i < 2; i++) {
        int idx = tid + i * 256;                 // 0..511 16B-chunks
        int r = idx >> 2, c = idx & 3;
        uint32_t d = sw64((uint32_t)idx * 16);
        size_t goA = (size_t)(m0 + r) * 1024 + k0 + c * 8;
        size_t goB = (size_t)(n0 + r) * 1024 + k0 + c * 8;
        cp_async16(st +           d, Ahi + goA);
        cp_async16(st + ARR     + d, Alo + goA);
        cp_async16(st + 2 * ARR + d, Bhi + goB);
        cp_async16(st + 3 * ARR + d, Blo + goB);
    }
    CP_COMMIT();
}

template<bool QKV_EP>
__global__ void __launch_bounds__(256, 2) gemm_mma(
    const __nv_bfloat16* __restrict__ Ahi, const __nv_bfloat16* __restrict__ Alo,
    const __nv_bfloat16* __restrict__ Bhi, const __nv_bfloat16* __restrict__ Blo,
    const float* __restrict__ bias, float* __restrict__ Cout, int N)
{
    extern __shared__ __align__(128) char smem[];
    const uint32_t sb = smem_u32(smem);
    const int tid  = threadIdx.x;
    const int wid  = tid >> 5;
    const int lane = tid & 31;
    const int m0 = blockIdx.y * 128;
    const int n0 = blockIdx.x * 128;
    const int warpM = (wid >> 2) * 64;
    const int warpN = (wid & 3) * 32;

    float acc[4][4][4];
    #pragma unroll
    for (int i = 0; i < 4; i++)
        #pragma unroll
        for (int j = 0; j < 4; j++)
            #pragma unroll
            for (int e = 0; e < 4; e++) acc[i][j][e] = 0.f;

    // logical (pre-swizzle) base offsets within a 128x64B array
    const uint32_t aL = (uint32_t)((warpM + (lane & 15)) * 64 + (lane >> 4) * 16);
    const int brow = (lane & 7) + ((lane >> 4) << 3);
    const uint32_t bL = (uint32_t)((warpN + brow) * 64 + ((lane >> 3) & 1) * 16);

    load_stage(tid, 0, sb, Ahi, Alo, Bhi, Blo, m0, n0);
    load_stage(tid, 1, sb, Ahi, Alo, Bhi, Blo, m0, n0);

    for (int kt = 0; kt < NK; kt++) {
        if (kt + 1 < NK) asm volatile("cp.async.wait_group 1;" ::: "memory");
        else             asm volatile("cp.async.wait_group 0;" ::: "memory");
        __syncthreads();
        if (kt + 2 < NK)
            load_stage(tid, kt + 2, sb, Ahi, Alo, Bhi, Blo, m0, n0);

        const uint32_t st = sb + (uint32_t)((kt % NSTG) * STAGE);
        #pragma unroll
        for (int ks = 0; ks < 2; ks++) {
            uint32_t ah[4][4], al[4][4], bh[4][2], bl[4][2];
            #pragma unroll
            for (int mt = 0; mt < 4; mt++) {
                uint32_t d = sw64(aL + (uint32_t)(mt * 1024 + ks * 32));
                ldsm4(ah[mt], st + d);
                ldsm4(al[mt], st + ARR + d);
            }
            #pragma unroll
            for (int np = 0; np < 2; np++) {
                uint32_t d = sw64(bL + (uint32_t)(np * 1024 + ks * 32));
                uint32_t r[4];
                ldsm4(r, st + 2 * ARR + d);
                bh[np*2][0] = r[0]; bh[np*2][1] = r[1];
                bh[np*2+1][0] = r[2]; bh[np*2+1][1] = r[3];
                ldsm4(r, st + 3 * ARR + d);
                bl[np*2][0] = r[0]; bl[np*2][1] = r[1];
                bl[np*2+1][0] = r[2]; bl[np*2+1][1] = r[3];
            }
            // term-major: 16 independent MMAs between accumulator reuses
            #pragma unroll
            for (int mt = 0; mt < 4; mt++)
                #pragma unroll
                for (int nt = 0; nt < 4; nt++)
                    mma16816(acc[mt][nt], ah[mt], bh[nt]);
            #pragma unroll
            for (int mt = 0; mt < 4; mt++)
                #pragma unroll
                for (int nt = 0; nt < 4; nt++)
                    mma16816(acc[mt][nt], ah[mt], bl[nt]);
            #pragma unroll
            for (int mt = 0; mt < 4; mt++)
                #pragma unroll
                for (int nt = 0; nt < 4; nt++)
                    mma16816(acc[mt][nt], al[mt], bh[nt]);
        }
    }

    const int gid = lane >> 2;
    const int tig = lane & 3;
    #pragma unroll
    for (int mt = 0; mt < 4; mt++) {
        #pragma unroll
        for (int nt = 0; nt < 4; nt++) {
            int n = n0 + warpN + nt * 8 + tig * 2;
            float bx = bias[n], by = bias[n + 1];
            #pragma unroll
            for (int half = 0; half < 2; half++) {
                int m = m0 + warpM + mt * 16 + gid + half * 8;
                float vx = acc[mt][nt][half * 2 + 0] + bx;
                float vy = acc[mt][nt][half * 2 + 1] + by;
                if (QKV_EP) {
                    int which = n >> 10;
                    int hh = (n >> 6) & 15;
                    int dd = n & 63;
                    int bb = m >> 11;
                    int tt = m & 2047;
                    if (which == 0) { vx *= 0.125f; vy *= 0.125f; }
                    uint32_t hi, lo;
                    split2(vx, vy, hi, lo);
                    size_t off = (((size_t)bb * HH + hh) * TT + tt) * DD + dd;
                    __nv_bfloat16* ph = (which == 0) ? g_q_hi : (which == 1) ? g_k_hi : g_v_hi;
                    __nv_bfloat16* pl = (which == 0) ? g_q_lo : (which == 1) ? g_k_lo : g_v_lo;
                    *(uint32_t*)(ph + off) = hi;
                    *(uint32_t*)(pl + off) = lo;
                } else {
                    float2 v; v.x = vx; v.y = vy;
                    *(float2*)(Cout + (size_t)m * N + n) = v;
                }
            }
        }
    }
}

// ---------------------------------------------------------------------------
// Tensor-core flash attention (split-bf16), dependency-spaced MMA order.
// ---------------------------------------------------------------------------
#define AT_ROWB 144
#define AT_TILE (64 * AT_ROWB)          // 9216 B
#define ATT_SMEM (2 * AT_TILE + 2 * 4 * AT_TILE)   // 92160 B

__global__ void __launch_bounds__(128) attn_mma()
{
    extern __shared__ __align__(128) char smem[];
    const uint32_t sb = smem_u32(smem);
    const int tid  = threadIdx.x;
    const int wid  = tid >> 5;
    const int lane = tid & 31;
    const int bh = blockIdx.y;
    const int q0 = blockIdx.x * 64;
    const int warpM = wid * 16;
    const size_t bhoff = (size_t)bh * TT * DD;

    const uint32_t kvbase0 = sb + 2 * AT_TILE;

    {
        const __nv_bfloat16* Qh = g_q_hi + bhoff + (size_t)q0 * DD;
        const __nv_bfloat16* Ql = g_q_lo + bhoff + (size_t)q0 * DD;
        for (int i = tid; i < 512; i += 128) {
            int r = i >> 3, c = i & 7;
            uint32_t d = (uint32_t)(r * AT_ROWB + c * 16);
            size_t go = (size_t)r * DD + c * 8;
            cp_async16(sb + d,          Qh + go);
            cp_async16(sb + AT_TILE + d, Ql + go);
        }
        CP_COMMIT();
    }

    const int njt = q0 / 64 + 1;

    {
        const __nv_bfloat16* Kh = g_k_hi + bhoff;
        const __nv_bfloat16* Kl = g_k_lo + bhoff;
        const __nv_bfloat16* Vh = g_v_hi + bhoff;
        const __nv_bfloat16* Vl = g_v_lo + bhoff;
        for (int i = tid; i < 512; i += 128) {
            int r = i >> 3, c = i & 7;
            uint32_t d = (uint32_t)(r * AT_ROWB + c * 16);
            size_t go = (size_t)r * DD + c * 8;
            cp_async16(kvbase0 + d,               Kh + go);
            cp_async16(kvbase0 + AT_TILE + d,     Kl + go);
            cp_async16(kvbase0 + 2 * AT_TILE + d, Vh + go);
            cp_async16(kvbase0 + 3 * AT_TILE + d, Vl + go);
        }
        CP_COMMIT();
    }

    asm volatile("cp.async.wait_group 1;" ::: "memory");
    __syncthreads();
    uint32_t qh[4][4], ql[4][4];
    const uint32_t a_off = (uint32_t)((warpM + (lane & 15)) * AT_ROWB + (lane >> 4) * 16);
    #pragma unroll
    for (int ks = 0; ks < 4; ks++) {
        ldsm4(qh[ks], sb + a_off + ks * 32);
        ldsm4(ql[ks], sb + AT_TILE + a_off + ks * 32);
    }

    float o[8][4];
    #pragma unroll
    for (int i = 0; i < 8; i++)
        #pragma unroll
        for (int e = 0; e < 4; e++) o[i][e] = 0.f;
    float m0 = -1e30f, m1 = -1e30f, l0 = 0.f, l1 = 0.f;

    const int brow = (lane & 7) + ((lane >> 4) << 3);
    const uint32_t b_off = (uint32_t)(brow * AT_ROWB + ((lane >> 3) & 1) * 16);
    const int vrow = (lane & 7) + ((lane >> 3) & 1) * 8;
    const uint32_t v_off = (uint32_t)(vrow * AT_ROWB + (lane >> 4) * 16);

    for (int jt = 0; jt < njt; jt++) {
        if (jt + 1 < njt) {
            uint32_t nb = sb + 2 * AT_TILE + (uint32_t)(((jt + 1) & 1) * 4 * AT_TILE);
            size_t jo = (size_t)(jt + 1) * 64 * DD;
            const __nv_bfloat16* Kh = g_k_hi + bhoff + jo;
            const __nv_bfloat16* Kl = g_k_lo + bhoff + jo;
            const __nv_bfloat16* Vh = g_v_hi + bhoff + jo;
            const __nv_bfloat16* Vl = g_v_lo + bhoff + jo;
            for (int i = tid; i < 512; i += 128) {
                int r = i >> 3, c = i & 7;
                uint32_t d = (uint32_t)(r * AT_ROWB + c * 16);
                size_t go = (size_t)r * DD + c * 8;
                cp_async16(nb + d,               Kh + go);
                cp_async16(nb + AT_TILE + d,     Kl + go);
                cp_async16(nb + 2 * AT_TILE + d, Vh + go);
                cp_async16(nb + 3 * AT_TILE + d, Vl + go);
            }
            CP_COMMIT();
            asm volatile("cp.async.wait_group 1;" ::: "memory");
        } else {
            asm volatile("cp.async.wait_group 0;" ::: "memory");
        }
        __syncthreads();

        const uint32_t kb = sb + 2 * AT_TILE + (uint32_t)((jt & 1) * 4 * AT_TILE);

        float s[8][4];
        #pragma unroll
        for (int i = 0; i < 8; i++)
            #pragma unroll
            for (int e = 0; e < 4; e++) s[i][e] = 0.f;

        #pragma unroll
        for (int ks = 0; ks < 4; ks++) {
            #pragma unroll
            for (int np = 0; np < 4; np++) {
                uint32_t rh[4], rl[4];
                uint32_t bd = kb + b_off + (uint32_t)(np * 16 * AT_ROWB) + ks * 32;
                ldsm4(rh, bd);
                ldsm4(rl, bd + AT_TILE);
                uint32_t bh0[2] = {rh[0], rh[1]}, bh1[2] = {rh[2], rh[3]};
                uint32_t bl0[2] = {rl[0], rl[1]}, bl1[2] = {rl[2], rl[3]};
                // interleave the two accumulators: dependent reuse distance 2
                mma16816(s[np*2],   qh[ks], bh0);
                mma16816(s[np*2+1], qh[ks], bh1);
                mma16816(s[np*2],   ql[ks], bh0);
                mma16816(s[np*2+1], ql[ks], bh1);
                mma16816(s[np*2],   qh[ks], bl0);
                mma16816(s[np*2+1], qh[ks], bl1);
            }
        }

        if (jt == njt - 1) {
            int r0 = warpM + (lane >> 2);
            #pragma unroll
            for (int nt = 0; nt < 8; nt++) {
                int c0 = nt * 8 + (lane & 3) * 2;
                #pragma unroll
                for (int e = 0; e < 4; e++) {
                    int row = r0 + (e >> 1) * 8;
                    int col = c0 + (e & 1);
                    if (col > row) s[nt][e] = -1e30f;
                }
            }
        }

        float tm0 = -1e30f, tm1 = -1e30f;
        #pragma unroll
        for (int nt = 0; nt < 8; nt++) {
            tm0 = fmaxf(tm0, fmaxf(s[nt][0], s[nt][1]));
            tm1 = fmaxf(tm1, fmaxf(s[nt][2], s[nt][3]));
        }
        tm0 = fmaxf(tm0, __shfl_xor_sync(0xffffffff, tm0, 1));
        tm0 = fmaxf(tm0, __shfl_xor_sync(0xffffffff, tm0, 2));
        tm1 = fmaxf(tm1, __shfl_xor_sync(0xffffffff, tm1, 1));
        tm1 = fmaxf(tm1, __shfl_xor_sync(0xffffffff, tm1, 2));

        float nm0 = fmaxf(m0, tm0), nm1 = fmaxf(m1, tm1);
        float c0s = __expf(m0 - nm0), c1s = __expf(m1 - nm1);
        m0 = nm0; m1 = nm1;

        float ls0 = 0.f, ls1 = 0.f;
        #pragma unroll
        for (int nt = 0; nt < 8; nt++) {
            s[nt][0] = __expf(s[nt][0] - nm0); ls0 += s[nt][0];
            s[nt][1] = __expf(s[nt][1] - nm0); ls0 += s[nt][1];
            s[nt][2] = __expf(s[nt][2] - nm1); ls1 += s[nt][2];
            s[nt][3] = __expf(s[nt][3] - nm1); ls1 += s[nt][3];
        }
        ls0 += __shfl_xor_sync(0xffffffff, ls0, 1);
        ls0 += __shfl_xor_sync(0xffffffff, ls0, 2);
        ls1 += __shfl_xor_sync(0xffffffff, ls1, 1);
        ls1 += __shfl_xor_sync(0xffffffff, ls1, 2);
        l0 = l0 * c0s + ls0;
        l1 = l1 * c1s + ls1;

        #pragma unroll
        for (int dt = 0; dt < 8; dt++) {
            o[dt][0] *= c0s; o[dt][1] *= c0s;
            o[dt][2] *= c1s; o[dt][3] *= c1s;
        }

        uint32_t ph[4][4], pl[4][4];
        #pragma unroll
        for (int ksv = 0; ksv < 4; ksv++) {
            split2(s[2*ksv][0],   s[2*ksv][1],   ph[ksv][0], pl[ksv][0]);
            split2(s[2*ksv][2],   s[2*ksv][3],   ph[ksv][1], pl[ksv][1]);
            split2(s[2*ksv+1][0], s[2*ksv+1][1], ph[ksv][2], pl[ksv][2]);
            split2(s[2*ksv+1][2], s[2*ksv+1][3], ph[ksv][3], pl[ksv][3]);
        }

        const uint32_t vb = kb + 2 * AT_TILE;
        #pragma unroll
        for (int ksv = 0; ksv < 4; ksv++) {
            #pragma unroll
            for (int dg = 0; dg < 4; dg++) {
                uint32_t rh[4], rl[4];
                uint32_t vd = vb + v_off + (uint32_t)(ksv * 16 * AT_ROWB) + dg * 32;
                ldsm4t(rh, vd);
                ldsm4t(rl, vd + AT_TILE);
                uint32_t vh0[2] = {rh[0], rh[1]}, vh1[2] = {rh[2], rh[3]};
                uint32_t vl0[2] = {rl[0], rl[1]}, vl1[2] = {rl[2], rl[3]};
                mma16816(o[dg*2],   ph[ksv], vh0);
                mma16816(o[dg*2+1], ph[ksv], vh1);
                mma16816(o[dg*2],   pl[ksv], vh0);
                mma16816(o[dg*2+1], pl[ksv], vh1);
                mma16816(o[dg*2],   ph[ksv], vl0);
                mma16816(o[dg*2+1], ph[ksv], vl1);
            }
        }
        __syncthreads();
    }

    float inv0 = 1.f / l0, inv1 = 1.f / l1;
    int qi = q0 + warpM + (lane >> 2);
    size_t ro0 = ((size_t)(bh >> 4) * TT + qi) * CC + (size_t)(bh & 15) * DD;
    size_t ro1 = ro0 + (size_t)8 * CC;
    #pragma unroll
    for (int dt = 0; dt < 8; dt++) {
        int col = dt * 8 + (lane & 3) * 2;
        uint32_t hi, lo;
        split2(o[dt][0] * inv0, o[dt][1] * inv0, hi, lo);
        *(uint32_t*)(g_att_hi + ro0 + col) = hi;
        *(uint32_t*)(g_att_lo + ro0 + col) = lo;
        split2(o[dt][2] * inv1, o[dt][3] * inv1, hi, lo);
        *(uint32_t*)(g_att_hi + ro1 + col) = hi;
        *(uint32_t*)(g_att_lo + ro1 + col) = lo;
    }
}

// ---------------------------------------------------------------------------
extern "C" void kernel_launch(void* const* d_in, const int* in_sizes, int n_in,
                              void* d_out, int out_size)
{
    const float* x      = (const float*)d_in[0];
    const float* w_attn = (const float*)d_in[1];
    const float* b_attn = (const float*)d_in[2];
    const float* w_proj = (const float*)d_in[3];
    const float* b_proj = (const float*)d_in[4];
    float* out = (float*)d_out;

    __nv_bfloat16 *xh, *xl, *wqh, *wql, *wph, *wpl, *ah, *al;
    cudaGetSymbolAddress((void**)&xh,  g_x_hi);
    cudaGetSymbolAddress((void**)&xl,  g_x_lo);
    cudaGetSymbolAddress((void**)&wqh, g_wq_hi);
    cudaGetSymbolAddress((void**)&wql, g_wq_lo);
    cudaGetSymbolAddress((void**)&wph, g_wp_hi);
    cudaGetSymbolAddress((void**)&wpl, g_wp_lo);
    cudaGetSymbolAddress((void**)&ah,  g_att_hi);
    cudaGetSymbolAddress((void**)&al,  g_att_lo);

    cudaFuncSetAttribute(gemm_mma<true>,  cudaFuncAttributeMaxDynamicSharedMemorySize, GEMM_SMEM);
    cudaFuncSetAttribute(gemm_mma<false>, cudaFuncAttributeMaxDynamicSharedMemorySize, GEMM_SMEM);
    cudaFuncSetAttribute(attn_mma, cudaFuncAttributeMaxDynamicSharedMemorySize, ATT_SMEM);

    split_kernel<<<4096, 256>>>(x, xh, xl);
    tsplit_kernel<<<dim3(96, 32), dim3(32, 32)>>>(w_attn, wqh, wql, 3072, 1024);
    tsplit_kernel<<<dim3(32, 32), dim3(32, 32)>>>(w_proj, wph, wpl, 1024, 1024);

    gemm_mma<true><<<dim3(24, 32), 256, GEMM_SMEM>>>(xh, xl, wqh, wql, b_attn, nullptr, 3072);
    attn_mma<<<dim3(TT / 64, BB * HH), 128, ATT_SMEM>>>();
    gemm_mma<false><<<dim3(8, 32), 256, GEMM_SMEM>>>(ah, al, wph, wpl, b_proj, out, 1024);
}

// round 6
// speedup vs baseline: 7.2080x; 1.0462x over previous
#include <cuda_runtime.h>
#include <cuda_bf16.h>
#include <cstdint>

#define BB 2
#define TT 2048
#define CC 1024
#define HH 16
#define DD 64
#define BHTD (BB*HH*TT*DD)   // 4,194,304

// ---------------------------------------------------------------------------
// Scratch (__device__ globals; allocation-free rule)
// ---------------------------------------------------------------------------
__device__ __align__(16) __nv_bfloat16 g_x_hi[4096ll * 1024];
__device__ __align__(16) __nv_bfloat16 g_x_lo[4096ll * 1024];
__device__ __align__(16) __nv_bfloat16 g_wq_hi[3072ll * 1024];       // w_attn^T [N,K]
__device__ __align__(16) __nv_bfloat16 g_wq_lo[3072ll * 1024];
__device__ __align__(16) __nv_bfloat16 g_wp_hi[1024ll * 1024];       // w_proj^T [N,K]
__device__ __align__(16) __nv_bfloat16 g_wp_lo[1024ll * 1024];
__device__ __align__(16) __nv_bfloat16 g_att_hi[4096ll * 1024];      // attn out split [M,K]
__device__ __align__(16) __nv_bfloat16 g_att_lo[4096ll * 1024];
// QKV split outputs, [B*H, T, D]
__device__ __align__(16) __nv_bfloat16 g_q_hi[BHTD];
__device__ __align__(16) __nv_bfloat16 g_q_lo[BHTD];
__device__ __align__(16) __nv_bfloat16 g_k_hi[BHTD];
__device__ __align__(16) __nv_bfloat16 g_k_lo[BHTD];
__device__ __align__(16) __nv_bfloat16 g_v_hi[BHTD];
__device__ __align__(16) __nv_bfloat16 g_v_lo[BHTD];

// ---------------------------------------------------------------------------
// Helpers
// ---------------------------------------------------------------------------
__device__ __forceinline__ uint32_t smem_u32(const void* p) {
    uint32_t a;
    asm("{ .reg .u64 t; cvta.to.shared.u64 t, %1; cvt.u32.u64 %0, t; }" : "=r"(a) : "l"(p));
    return a;
}
__device__ __forceinline__ void cp_async16(uint32_t dst, const void* src) {
    asm volatile("cp.async.cg.shared.global [%0], [%1], 16;" :: "r"(dst), "l"(src));
}
#define CP_COMMIT() asm volatile("cp.async.commit_group;" ::: "memory")
__device__ __forceinline__ uint32_t sw64(uint32_t off) {      // SW64 XOR swizzle
    return off ^ ((off >> 3) & 0x30);
}

__device__ __forceinline__ void ldsm4(uint32_t* r, uint32_t addr) {
    asm volatile("ldmatrix.sync.aligned.m8n8.x4.shared.b16 {%0,%1,%2,%3}, [%4];"
        : "=r"(r[0]), "=r"(r[1]), "=r"(r[2]), "=r"(r[3]) : "r"(addr));
}
__device__ __forceinline__ void ldsm4t(uint32_t* r, uint32_t addr) {
    asm volatile("ldmatrix.sync.aligned.m8n8.x4.trans.shared.b16 {%0,%1,%2,%3}, [%4];"
        : "=r"(r[0]), "=r"(r[1]), "=r"(r[2]), "=r"(r[3]) : "r"(addr));
}
__device__ __forceinline__ void mma16816(float* d, const uint32_t* a, const uint32_t* b) {
    asm volatile("mma.sync.aligned.m16n8k16.row.col.f32.bf16.bf16.f32 "
        "{%0,%1,%2,%3}, {%4,%5,%6,%7}, {%8,%9}, {%0,%1,%2,%3};"
        : "+f"(d[0]), "+f"(d[1]), "+f"(d[2]), "+f"(d[3])
        : "r"(a[0]), "r"(a[1]), "r"(a[2]), "r"(a[3]), "r"(b[0]), "r"(b[1]));
}
__device__ __forceinline__ void split2(float x, float y, uint32_t& hi, uint32_t& lo) {
    __nv_bfloat16 hx = __float2bfloat16_rn(x), hy = __float2bfloat16_rn(y);
    __nv_bfloat16 lx = __float2bfloat16_rn(x - __bfloat162float(hx));
    __nv_bfloat16 ly = __float2bfloat16_rn(y - __bfloat162float(hy));
    __nv_bfloat162 h2 = __halves2bfloat162(hx, hy);
    __nv_bfloat162 l2 = __halves2bfloat162(lx, ly);
    hi = *reinterpret_cast<uint32_t*>(&h2);
    lo = *reinterpret_cast<uint32_t*>(&l2);
}

// ---------------------------------------------------------------------------
// Prepass kernels
// ---------------------------------------------------------------------------
__global__ void split_kernel(const float* __restrict__ X,
                             __nv_bfloat16* __restrict__ hi,
                             __nv_bfloat16* __restrict__ lo)
{
    int i = blockIdx.x * blockDim.x + threadIdx.x;
    float4 v = ((const float4*)X)[i];
    uint32_t h0, l0, h1, l1;
    split2(v.x, v.y, h0, l0);
    split2(v.z, v.w, h1, l1);
    *(uint32_t*)(hi + (size_t)i * 4)     = h0;
    *(uint32_t*)(hi + (size_t)i * 4 + 2) = h1;
    *(uint32_t*)(lo + (size_t)i * 4)     = l0;
    *(uint32_t*)(lo + (size_t)i * 4 + 2) = l1;
}

__global__ void tsplit_kernel(const float* __restrict__ W,
                              __nv_bfloat16* __restrict__ Thi,
                              __nv_bfloat16* __restrict__ Tlo,
                              int Ncols, int Krows)
{
    __shared__ float ts[32][33];
    int n0 = blockIdx.x * 32, k0 = blockIdx.y * 32;
    int tx = threadIdx.x, ty = threadIdx.y;
    ts[ty][tx] = W[(size_t)(k0 + ty) * Ncols + n0 + tx];
    __syncthreads();
    float v = ts[tx][ty];
    __nv_bfloat16 h = __float2bfloat16_rn(v);
    size_t o = (size_t)(n0 + ty) * Krows + k0 + tx;
    Thi[o] = h;
    Tlo[o] = __float2bfloat16_rn(v - __bfloat162float(h));
}

// ---------------------------------------------------------------------------
// bf16x3 GEMM via mma.sync. 128 threads (4 warps), warp tile 64x64,
// block 128x128, BK=32, 3-stage SW64 smem (32KB/stage) -> 2 CTAs/SM.
// Per k16-step: 16 ldsm.x4 feed 96 MMAs (6:1), term-major order.
// ---------------------------------------------------------------------------
#define ARR   8192                  // 128 rows x 64B
#define STAGE (4 * ARR)             // Ahi,Alo,Bhi,Blo = 32768
#define NSTG 3
#define GEMM_SMEM (NSTG * STAGE)    // 98304
#define NK 32

__device__ __forceinline__ void load_stage(
    int tid, int kt, uint32_t sbase,
    const __nv_bfloat16* Ahi, const __nv_bfloat16* Alo,
    const __nv_bfloat16* Bhi, const __nv_bfloat16* Blo,
    int m0, int n0)
{
    const uint32_t st = sbase + (uint32_t)((kt % NSTG) * STAGE);
    const int k0 = kt * 32;
    #pragma unroll
    for (int i = 0; i < 4; i++) {
        int idx = tid + i * 128;                 // 0..511 16B-chunks
        int r = idx >> 2, c = idx & 3;
        uint32_t d = sw64((uint32_t)idx * 16);
        size_t goA = (size_t)(m0 + r) * 1024 + k0 + c * 8;
        size_t goB = (size_t)(n0 + r) * 1024 + k0 + c * 8;
        cp_async16(st +           d, Ahi + goA);
        cp_async16(st + ARR     + d, Alo + goA);
        cp_async16(st + 2 * ARR + d, Bhi + goB);
        cp_async16(st + 3 * ARR + d, Blo + goB);
    }
    CP_COMMIT();
}

template<bool QKV_EP>
__global__ void __launch_bounds__(128, 2) gemm_mma(
    const __nv_bfloat16* __restrict__ Ahi, const __nv_bfloat16* __restrict__ Alo,
    const __nv_bfloat16* __restrict__ Bhi, const __nv_bfloat16* __restrict__ Blo,
    const float* __restrict__ bias, float* __restrict__ Cout, int N)
{
    extern __shared__ __align__(128) char smem[];
    const uint32_t sb = smem_u32(smem);
    const int tid  = threadIdx.x;
    const int wid  = tid >> 5;
    const int lane = tid & 31;
    const int m0 = blockIdx.y * 128;
    const int n0 = blockIdx.x * 128;
    const int warpM = (wid >> 1) * 64;     // 0 or 64
    const int warpN = (wid & 1) * 64;      // 0 or 64

    float acc[4][8][4];
    #pragma unroll
    for (int i = 0; i < 4; i++)
        #pragma unroll
        for (int j = 0; j < 8; j++)
            #pragma unroll
            for (int e = 0; e < 4; e++) acc[i][j][e] = 0.f;

    // logical (pre-swizzle) base offsets within a 128x64B array
    const uint32_t aL = (uint32_t)((warpM + (lane & 15)) * 64 + (lane >> 4) * 16);
    const int brow = (lane & 7) + ((lane >> 4) << 3);
    const uint32_t bL = (uint32_t)((warpN + brow) * 64 + ((lane >> 3) & 1) * 16);

    load_stage(tid, 0, sb, Ahi, Alo, Bhi, Blo, m0, n0);
    load_stage(tid, 1, sb, Ahi, Alo, Bhi, Blo, m0, n0);

    for (int kt = 0; kt < NK; kt++) {
        if (kt + 1 < NK) asm volatile("cp.async.wait_group 1;" ::: "memory");
        else             asm volatile("cp.async.wait_group 0;" ::: "memory");
        __syncthreads();
        if (kt + 2 < NK)
            load_stage(tid, kt + 2, sb, Ahi, Alo, Bhi, Blo, m0, n0);

        const uint32_t st = sb + (uint32_t)((kt % NSTG) * STAGE);
        #pragma unroll
        for (int ks = 0; ks < 2; ks++) {
            uint32_t ah[4][4], al[4][4], bh[8][2], bl[8][2];
            #pragma unroll
            for (int mt = 0; mt < 4; mt++) {
                uint32_t d = sw64(aL + (uint32_t)(mt * 1024 + ks * 32));
                ldsm4(ah[mt], st + d);
                ldsm4(al[mt], st + ARR + d);
            }
            #pragma unroll
            for (int np = 0; np < 4; np++) {
                uint32_t d = sw64(bL + (uint32_t)(np * 1024 + ks * 32));
                uint32_t r[4];
                ldsm4(r, st + 2 * ARR + d);
                bh[np*2][0] = r[0]; bh[np*2][1] = r[1];
                bh[np*2+1][0] = r[2]; bh[np*2+1][1] = r[3];
                ldsm4(r, st + 3 * ARR + d);
                bl[np*2][0] = r[0]; bl[np*2][1] = r[1];
                bl[np*2+1][0] = r[2]; bl[np*2+1][1] = r[3];
            }
            // term-major: 32 independent MMAs between accumulator reuses
            #pragma unroll
            for (int mt = 0; mt < 4; mt++)
                #pragma unroll
                for (int nt = 0; nt < 8; nt++)
                    mma16816(acc[mt][nt], ah[mt], bh[nt]);
            #pragma unroll
            for (int mt = 0; mt < 4; mt++)
                #pragma unroll
                for (int nt = 0; nt < 8; nt++)
                    mma16816(acc[mt][nt], ah[mt], bl[nt]);
            #pragma unroll
            for (int mt = 0; mt < 4; mt++)
                #pragma unroll
                for (int nt = 0; nt < 8; nt++)
                    mma16816(acc[mt][nt], al[mt], bh[nt]);
        }
    }

    const int gid = lane >> 2;
    const int tig = lane & 3;
    #pragma unroll
    for (int mt = 0; mt < 4; mt++) {
        #pragma unroll
        for (int nt = 0; nt < 8; nt++) {
            int n = n0 + warpN + nt * 8 + tig * 2;
            float bx = bias[n], by = bias[n + 1];
            #pragma unroll
            for (int half = 0; half < 2; half++) {
                int m = m0 + warpM + mt * 16 + gid + half * 8;
                float vx = acc[mt][nt][half * 2 + 0] + bx;
                float vy = acc[mt][nt][half * 2 + 1] + by;
                if (QKV_EP) {
                    int which = n >> 10;
                    int hh = (n >> 6) & 15;
                    int dd = n & 63;
                    int bb = m >> 11;
                    int tt = m & 2047;
                    if (which == 0) { vx *= 0.125f; vy *= 0.125f; }
                    uint32_t hi, lo;
                    split2(vx, vy, hi, lo);
                    size_t off = (((size_t)bb * HH + hh) * TT + tt) * DD + dd;
                    __nv_bfloat16* ph = (which == 0) ? g_q_hi : (which == 1) ? g_k_hi : g_v_hi;
                    __nv_bfloat16* pl = (which == 0) ? g_q_lo : (which == 1) ? g_k_lo : g_v_lo;
                    *(uint32_t*)(ph + off) = hi;
                    *(uint32_t*)(pl + off) = lo;
                } else {
                    float2 v; v.x = vx; v.y = vy;
                    *(float2*)(Cout + (size_t)m * N + n) = v;
                }
            }
        }
    }
}

// ---------------------------------------------------------------------------
// Tensor-core flash attention (split-bf16), dependency-spaced MMA order.
// ---------------------------------------------------------------------------
#define AT_ROWB 144
#define AT_TILE (64 * AT_ROWB)          // 9216 B
#define ATT_SMEM (2 * AT_TILE + 2 * 4 * AT_TILE)   // 92160 B

__global__ void __launch_bounds__(128) attn_mma()
{
    extern __shared__ __align__(128) char smem[];
    const uint32_t sb = smem_u32(smem);
    const int tid  = threadIdx.x;
    const int wid  = tid >> 5;
    const int lane = tid & 31;
    const int bh = blockIdx.y;
    const int q0 = blockIdx.x * 64;
    const int warpM = wid * 16;
    const size_t bhoff = (size_t)bh * TT * DD;

    const uint32_t kvbase0 = sb + 2 * AT_TILE;

    {
        const __nv_bfloat16* Qh = g_q_hi + bhoff + (size_t)q0 * DD;
        const __nv_bfloat16* Ql = g_q_lo + bhoff + (size_t)q0 * DD;
        for (int i = tid; i < 512; i += 128) {
            int r = i >> 3, c = i & 7;
            uint32_t d = (uint32_t)(r * AT_ROWB + c * 16);
            size_t go = (size_t)r * DD + c * 8;
            cp_async16(sb + d,          Qh + go);
            cp_async16(sb + AT_TILE + d, Ql + go);
        }
        CP_COMMIT();
    }

    const int njt = q0 / 64 + 1;

    {
        const __nv_bfloat16* Kh = g_k_hi + bhoff;
        const __nv_bfloat16* Kl = g_k_lo + bhoff;
        const __nv_bfloat16* Vh = g_v_hi + bhoff;
        const __nv_bfloat16* Vl = g_v_lo + bhoff;
        for (int i = tid; i < 512; i += 128) {
            int r = i >> 3, c = i & 7;
            uint32_t d = (uint32_t)(r * AT_ROWB + c * 16);
            size_t go = (size_t)r * DD + c * 8;
            cp_async16(kvbase0 + d,               Kh + go);
            cp_async16(kvbase0 + AT_TILE + d,     Kl + go);
            cp_async16(kvbase0 + 2 * AT_TILE + d, Vh + go);
            cp_async16(kvbase0 + 3 * AT_TILE + d, Vl + go);
        }
        CP_COMMIT();
    }

    asm volatile("cp.async.wait_group 1;" ::: "memory");
    __syncthreads();
    uint32_t qh[4][4], ql[4][4];
    const uint32_t a_off = (uint32_t)((warpM + (lane & 15)) * AT_ROWB + (lane >> 4) * 16);
    #pragma unroll
    for (int ks = 0; ks < 4; ks++) {
        ldsm4(qh[ks], sb + a_off + ks * 32);
        ldsm4(ql[ks], sb + AT_TILE + a_off + ks * 32);
    }

    float o[8][4];
    #pragma unroll
    for (int i = 0; i < 8; i++)
        #pragma unroll
        for (int e = 0; e < 4; e++) o[i][e] = 0.f;
    float m0 = -1e30f, m1 = -1e30f, l0 = 0.f, l1 = 0.f;

    const int brow = (lane & 7) + ((lane >> 4) << 3);
    const uint32_t b_off = (uint32_t)(brow * AT_ROWB + ((lane >> 3) & 1) * 16);
    const int vrow = (lane & 7) + ((lane >> 3) & 1) * 8;
    const uint32_t v_off = (uint32_t)(vrow * AT_ROWB + (lane >> 4) * 16);

    for (int jt = 0; jt < njt; jt++) {
        if (jt + 1 < njt) {
            uint32_t nb = sb + 2 * AT_TILE + (uint32_t)(((jt + 1) & 1) * 4 * AT_TILE);
            size_t jo = (size_t)(jt + 1) * 64 * DD;
            const __nv_bfloat16* Kh = g_k_hi + bhoff + jo;
            const __nv_bfloat16* Kl = g_k_lo + bhoff + jo;
            const __nv_bfloat16* Vh = g_v_hi + bhoff + jo;
            const __nv_bfloat16* Vl = g_v_lo + bhoff + jo;
            for (int i = tid; i < 512; i += 128) {
                int r = i >> 3, c = i & 7;
                uint32_t d = (uint32_t)(r * AT_ROWB + c * 16);
                size_t go = (size_t)r * DD + c * 8;
                cp_async16(nb + d,               Kh + go);
                cp_async16(nb + AT_TILE + d,     Kl + go);
                cp_async16(nb + 2 * AT_TILE + d, Vh + go);
                cp_async16(nb + 3 * AT_TILE + d, Vl + go);
            }
            CP_COMMIT();
            asm volatile("cp.async.wait_group 1;" ::: "memory");
        } else {
            asm volatile("cp.async.wait_group 0;" ::: "memory");
        }
        __syncthreads();

        const uint32_t kb = sb + 2 * AT_TILE + (uint32_t)((jt & 1) * 4 * AT_TILE);

        float s[8][4];
        #pragma unroll
        for (int i = 0; i < 8; i++)
            #pragma unroll
            for (int e = 0; e < 4; e++) s[i][e] = 0.f;

        #pragma unroll
        for (int ks = 0; ks < 4; ks++) {
            #pragma unroll
            for (int np = 0; np < 4; np++) {
                uint32_t rh[4], rl[4];
                uint32_t bd = kb + b_off + (uint32_t)(np * 16 * AT_ROWB) + ks * 32;
                ldsm4(rh, bd);
                ldsm4(rl, bd + AT_TILE);
                uint32_t bh0[2] = {rh[0], rh[1]}, bh1[2] = {rh[2], rh[3]};
                uint32_t bl0[2] = {rl[0], rl[1]}, bl1[2] = {rl[2], rl[3]};
                mma16816(s[np*2],   qh[ks], bh0);
                mma16816(s[np*2+1], qh[ks], bh1);
                mma16816(s[np*2],   ql[ks], bh0);
                mma16816(s[np*2+1], ql[ks], bh1);
                mma16816(s[np*2],   qh[ks], bl0);
                mma16816(s[np*2+1], qh[ks], bl1);
            }
        }

        if (jt == njt - 1) {
            int r0 = warpM + (lane >> 2);
            #pragma unroll
            for (int nt = 0; nt < 8; nt++) {
                int c0 = nt * 8 + (lane & 3) * 2;
                #pragma unroll
                for (int e = 0; e < 4; e++) {
                    int row = r0 + (e >> 1) * 8;
                    int col = c0 + (e & 1);
                    if (col > row) s[nt][e] = -1e30f;
                }
            }
        }

        float tm0 = -1e30f, tm1 = -1e30f;
        #pragma unroll
        for (int nt = 0; nt < 8; nt++) {
            tm0 = fmaxf(tm0, fmaxf(s[nt][0], s[nt][1]));
            tm1 = fmaxf(tm1, fmaxf(s[nt][2], s[nt][3]));
        }
        tm0 = fmaxf(tm0, __shfl_xor_sync(0xffffffff, tm0, 1));
        tm0 = fmaxf(tm0, __shfl_xor_sync(0xffffffff, tm0, 2));
        tm1 = fmaxf(tm1, __shfl_xor_sync(0xffffffff, tm1, 1));
        tm1 = fmaxf(tm1, __shfl_xor_sync(0xffffffff, tm1, 2));

        float nm0 = fmaxf(m0, tm0), nm1 = fmaxf(m1, tm1);
        float c0s = __expf(m0 - nm0), c1s = __expf(m1 - nm1);
        m0 = nm0; m1 = nm1;

        float ls0 = 0.f, ls1 = 0.f;
        #pragma unroll
        for (int nt = 0; nt < 8; nt++) {
            s[nt][0] = __expf(s[nt][0] - nm0); ls0 += s[nt][0];
            s[nt][1] = __expf(s[nt][1] - nm0); ls0 += s[nt][1];
            s[nt][2] = __expf(s[nt][2] - nm1); ls1 += s[nt][2];
            s[nt][3] = __expf(s[nt][3] - nm1); ls1 += s[nt][3];
        }
        ls0 += __shfl_xor_sync(0xffffffff, ls0, 1);
        ls0 += __shfl_xor_sync(0xffffffff, ls0, 2);
        ls1 += __shfl_xor_sync(0xffffffff, ls1, 1);
        ls1 += __shfl_xor_sync(0xffffffff, ls1, 2);
        l0 = l0 * c0s + ls0;
        l1 = l1 * c1s + ls1;

        #pragma unroll
        for (int dt = 0; dt < 8; dt++) {
            o[dt][0] *= c0s; o[dt][1] *= c0s;
            o[dt][2] *= c1s; o[dt][3] *= c1s;
        }

        uint32_t ph[4][4], pl[4][4];
        #pragma unroll
        for (int ksv = 0; ksv < 4; ksv++) {
            split2(s[2*ksv][0],   s[2*ksv][1],   ph[ksv][0], pl[ksv][0]);
            split2(s[2*ksv][2],   s[2*ksv][3],   ph[ksv][1], pl[ksv][1]);
            split2(s[2*ksv+1][0], s[2*ksv+1][1], ph[ksv][2], pl[ksv][2]);
            split2(s[2*ksv+1][2], s[2*ksv+1][3], ph[ksv][3], pl[ksv][3]);
        }

        const uint32_t vb = kb + 2 * AT_TILE;
        #pragma unroll
        for (int ksv = 0; ksv < 4; ksv++) {
            #pragma unroll
            for (int dg = 0; dg < 4; dg++) {
                uint32_t rh[4], rl[4];
                uint32_t vd = vb + v_off + (uint32_t)(ksv * 16 * AT_ROWB) + dg * 32;
                ldsm4t(rh, vd);
                ldsm4t(rl, vd + AT_TILE);
                uint32_t vh0[2] = {rh[0], rh[1]}, vh1[2] = {rh[2], rh[3]};
                uint32_t vl0[2] = {rl[0], rl[1]}, vl1[2] = {rl[2], rl[3]};
                mma16816(o[dg*2],   ph[ksv], vh0);
                mma16816(o[dg*2+1], ph[ksv], vh1);
                mma16816(o[dg*2],   pl[ksv], vh0);
                mma16816(o[dg*2+1], pl[ksv], vh1);
                mma16816(o[dg*2],   ph[ksv], vl0);
                mma16816(o[dg*2+1], ph[ksv], vl1);
            }
        }
        __syncthreads();
    }

    float inv0 = 1.f / l0, inv1 = 1.f / l1;
    int qi = q0 + warpM + (lane >> 2);
    size_t ro0 = ((size_t)(bh >> 4) * TT + qi) * CC + (size_t)(bh & 15) * DD;
    size_t ro1 = ro0 + (size_t)8 * CC;
    #pragma unroll
    for (int dt = 0; dt < 8; dt++) {
        int col = dt * 8 + (lane & 3) * 2;
        uint32_t hi, lo;
        split2(o[dt][0] * inv0, o[dt][1] * inv0, hi, lo);
        *(uint32_t*)(g_att_hi + ro0 + col) = hi;
        *(uint32_t*)(g_att_lo + ro0 + col) = lo;
        split2(o[dt][2] * inv1, o[dt][3] * inv1, hi, lo);
        *(uint32_t*)(g_att_hi + ro1 + col) = hi;
        *(uint32_t*)(g_att_lo + ro1 + col) = lo;
    }
}

// ---------------------------------------------------------------------------
extern "C" void kernel_launch(void* const* d_in, const int* in_sizes, int n_in,
                              void* d_out, int out_size)
{
    const float* x      = (const float*)d_in[0];
    const float* w_attn = (const float*)d_in[1];
    const float* b_attn = (const float*)d_in[2];
    const float* w_proj = (const float*)d_in[3];
    const float* b_proj = (const float*)d_in[4];
    float* out = (float*)d_out;

    __nv_bfloat16 *xh, *xl, *wqh, *wql, *wph, *wpl, *ah, *al;
    cudaGetSymbolAddress((void**)&xh,  g_x_hi);
    cudaGetSymbolAddress((void**)&xl,  g_x_lo);
    cudaGetSymbolAddress((void**)&wqh, g_wq_hi);
    cudaGetSymbolAddress((void**)&wql, g_wq_lo);
    cudaGetSymbolAddress((void**)&wph, g_wp_hi);
    cudaGetSymbolAddress((void**)&wpl, g_wp_lo);
    cudaGetSymbolAddress((void**)&ah,  g_att_hi);
    cudaGetSymbolAddress((void**)&al,  g_att_lo);

    cudaFuncSetAttribute(gemm_mma<true>,  cudaFuncAttributeMaxDynamicSharedMemorySize, GEMM_SMEM);
    cudaFuncSetAttribute(gemm_mma<false>, cudaFuncAttributeMaxDynamicSharedMemorySize, GEMM_SMEM);
    cudaFuncSetAttribute(attn_mma, cudaFuncAttributeMaxDynamicSharedMemorySize, ATT_SMEM);

    split_kernel<<<4096, 256>>>(x, xh, xl);
    tsplit_kernel<<<dim3(96, 32), dim3(32, 32)>>>(w_attn, wqh, wql, 3072, 1024);
    tsplit_kernel<<<dim3(32, 32), dim3(32, 32)>>>(w_proj, wph, wpl, 1024, 1024);

    gemm_mma<true><<<dim3(24, 32), 128, GEMM_SMEM>>>(xh, xl, wqh, wql, b_attn, nullptr, 3072);
    attn_mma<<<dim3(TT / 64, BB * HH), 128, ATT_SMEM>>>();
    gemm_mma<false><<<dim3(8, 32), 128, GEMM_SMEM>>>(ah, al, wph, wpl, b_proj, out, 1024);
}